// round 10
// baseline (speedup 1.0000x reference)
#include <cuda_runtime.h>
#include <cuda_fp16.h>
#include <cstdint>
#include <cstddef>
#include <math.h>

// Problem constants
#define BB   2
#define TT   2048
#define HH   2048
#define NH   16
#define NKV  8
#define HD   128
#define MM   (BB*TT)            // 4096 rows

// ---------------- scratch (static device globals; no allocation) -------------
__device__ __half g_qt[(size_t)BB * NH * TT * HD]; // [b,h,t,d] fp16
__device__ __half g_kt[(size_t)BB * NKV * TT * HD];
__device__ __half g_vt[(size_t)BB * NKV * TT * HD];
__device__ __half g_xh[(size_t)MM * HH];           // x fp16
__device__ __half g_wqkv[(size_t)4096 * 2048];     // [N=4096, K=2048] fp16 (Q|K|V rows)
__device__ __half g_wo[(size_t)2048 * 2048];       // Wo^T [N,K] fp16
__device__ __half g_ctx[(size_t)MM * HH];          // [b*T+t, h*HD+d] fp16
__device__ float g_cos[TT * 64];
__device__ float g_sin[TT * 64];

// ---------------- helpers ----------------------------------------------------
__device__ __forceinline__ uint32_t smem_u32(const void* p) {
    uint32_t a;
    asm("{ .reg .u64 t; cvta.to.shared.u64 t, %1; cvt.u32.u64 %0, t; }" : "=r"(a) : "l"(p));
    return a;
}

__device__ __forceinline__ void mma_f16(float c[4], const uint32_t a[4],
                                        uint32_t b0, uint32_t b1) {
    asm volatile(
        "mma.sync.aligned.m16n8k16.row.col.f32.f16.f16.f32 "
        "{%0,%1,%2,%3}, {%4,%5,%6,%7}, {%8,%9}, {%0,%1,%2,%3};\n"
        : "+f"(c[0]), "+f"(c[1]), "+f"(c[2]), "+f"(c[3])
        : "r"(a[0]), "r"(a[1]), "r"(a[2]), "r"(a[3]), "r"(b0), "r"(b1));
}

#define LDSM_X4(R0,R1,R2,R3,ADDR)                                              \
    asm volatile("ldmatrix.sync.aligned.m8n8.x4.shared.b16 {%0,%1,%2,%3}, [%4];" \
        : "=r"(R0), "=r"(R1), "=r"(R2), "=r"(R3) : "r"(ADDR))
#define LDSM_X4T(R0,R1,R2,R3,ADDR)                                             \
    asm volatile("ldmatrix.sync.aligned.m8n8.x4.trans.shared.b16 {%0,%1,%2,%3}, [%4];" \
        : "=r"(R0), "=r"(R1), "=r"(R2), "=r"(R3) : "r"(ADDR))

#define CP_ASYNC16(SMEM, GPTR) \
    asm volatile("cp.async.cg.shared.global [%0], [%1], 16;" :: "r"(SMEM), "l"(GPTR) : "memory")
#define CP_COMMIT() asm volatile("cp.async.commit_group;" ::: "memory")
#define CP_WAIT1()  asm volatile("cp.async.wait_group 1;" ::: "memory")

// ---------------- RoPE tables (fp64 angle, fp32 trig after reduction) ---------
__global__ void rope_table_kernel() {
    int t = blockIdx.x * 2 + (threadIdx.x >> 6);
    int j = threadIdx.x & 63;  // 0..63
    double inv = exp(-(double)j * (13.815510557964274 / 64.0)); // theta=1e6
    double ang = (double)t * inv;
    const double TWO_PI = 6.283185307179586476925286766559;
    double red = ang - TWO_PI * floor(ang * (1.0 / TWO_PI));
    float c, s;
    sincosf((float)red, &s, &c);
    g_cos[t * 64 + j] = c;
    g_sin[t * 64 + j] = s;
}

// ---------------- fp32 -> fp16 convert ----------------------------------------
__global__ __launch_bounds__(256) void conv_half_kernel(
    const float* __restrict__ in, __half* __restrict__ out, size_t n)
{
    size_t i = ((size_t)blockIdx.x * 256 + threadIdx.x) * 4;
    if (i < n) {
        float4 v = *(const float4*)(in + i);
        *(__half2*)(out + i)     = __floats2half2_rn(v.x, v.y);
        *(__half2*)(out + i + 2) = __floats2half2_rn(v.z, v.w);
    }
}

// ---------------- W [K,N] fp32 -> Wt [N,K] fp16 -------------------------------
__global__ __launch_bounds__(256) void wt_half_kernel(
    const float* __restrict__ W, __half* __restrict__ Wt, int K, int N_)
{
    __shared__ float t[32][33];
    int n0 = blockIdx.x * 32, k0 = blockIdx.y * 32;
    int tx = threadIdx.x & 31, ty = threadIdx.x >> 5;   // 32 x 8
    #pragma unroll
    for (int i = 0; i < 32; i += 8)
        t[ty + i][tx] = W[(size_t)(k0 + ty + i) * N_ + n0 + tx];
    __syncthreads();
    #pragma unroll
    for (int i = 0; i < 32; i += 8)
        Wt[(size_t)(n0 + ty + i) * K + k0 + tx] = __float2half(t[tx][ty + i]);
}

// =============== QKV GEMM with fused RMSNorm+RoPE+transpose epilogue ==========
// C-tile [128 tokens][128 dims] = exactly one head. BK=32, double-buffered,
// ldmatrix fragment loads. Epilogue: acc -> smem fp32, per-row rmsnorm (Q/K),
// RoPE, fp16 write to qt/kt/vt in [b,h,t,d].
#define GAS 40             // mainloop smem row stride (halves)
#define GSTG (128 * GAS)
#define SST 132            // epilogue fp32 tile stride (floats)
#define QKV_SMEM (128 * SST * 4)   // 67584 B (covers mainloop's 40960 too)

__global__ __launch_bounds__(256, 2) void gemm_qkv_kernel(
    const __half* __restrict__ A, const __half* __restrict__ Bm,
    __half* __restrict__ qt, __half* __restrict__ kt, __half* __restrict__ vt,
    const float* __restrict__ qnw, const float* __restrict__ knw)
{
    extern __shared__ char dsm[];
    __half* As = (__half*)dsm;
    __half* Bs = As + 2 * GSTG;
    const int K = HH;

    int tid = threadIdx.x;
    int wid = tid >> 5, lane = tid & 31;
    int g = lane >> 2, tg = lane & 3;
    int lr = lane & 7;
    int lm = (lane >> 3) & 1;
    int lh = lane >> 4;
    int sel = lane >> 3;
    int warpRow = wid >> 1, warpCol = wid & 1;
    int nb = blockIdx.x;               // head-block 0..31
    int brow = blockIdx.y * 128, bcol = nb * 128;

    int rowL[2], segL[2];
    #pragma unroll
    for (int it = 0; it < 2; ++it) {
        int idx = it * 256 + tid;
        rowL[it] = idx >> 2;
        segL[it] = (idx & 3) * 8;
    }
    const __half* ApL[2];
    const __half* BpL[2];
    #pragma unroll
    for (int it = 0; it < 2; ++it) {
        ApL[it] = A  + (size_t)(brow + rowL[it]) * K + segL[it];
        BpL[it] = Bm + (size_t)(bcol + rowL[it]) * K + segL[it];
    }

    uint32_t sA = smem_u32(As), sB = smem_u32(Bs);

    float acc[2][8][4];
    #pragma unroll
    for (int mi = 0; mi < 2; mi++)
        #pragma unroll
        for (int ni = 0; ni < 8; ni++)
            #pragma unroll
            for (int c = 0; c < 4; c++) acc[mi][ni][c] = 0.f;

    #pragma unroll
    for (int it = 0; it < 2; ++it) {
        *(int4*)&As[rowL[it] * GAS + segL[it]] = *(const int4*)ApL[it];
        *(int4*)&Bs[rowL[it] * GAS + segL[it]] = *(const int4*)BpL[it];
    }
    __syncthreads();

    int buf = 0;
    for (int k0 = 0; k0 < K; k0 += 32) {
        int4 pa[2], pb[2];
        bool more = (k0 + 32 < K);
        if (more) {
            #pragma unroll
            for (int it = 0; it < 2; ++it) {
                pa[it] = *(const int4*)(ApL[it] + k0 + 32);
                pb[it] = *(const int4*)(BpL[it] + k0 + 32);
            }
        }

        uint32_t bA = sA + buf * (GSTG * 2);
        uint32_t bB = sB + buf * (GSTG * 2);
        #pragma unroll
        for (int ks = 0; ks < 2; ++ks) {
            int kk = ks * 16;
            uint32_t af[2][4];
            #pragma unroll
            for (int mi = 0; mi < 2; mi++) {
                uint32_t addr = bA + (uint32_t)(((warpRow * 32 + mi * 16 + lr + lm * 8) * GAS
                                                 + kk + lh * 8) * 2);
                LDSM_X4(af[mi][0], af[mi][1], af[mi][2], af[mi][3], addr);
            }
            uint32_t bf[8][2];
            #pragma unroll
            for (int nbk = 0; nbk < 4; nbk++) {
                int n0 = warpCol * 64 + nbk * 16;
                uint32_t addr = bB + (uint32_t)(((n0 + lr + (sel >> 1) * 8) * GAS
                                                 + kk + (sel & 1) * 8) * 2);
                LDSM_X4(bf[2 * nbk][0], bf[2 * nbk][1], bf[2 * nbk + 1][0], bf[2 * nbk + 1][1], addr);
            }
            #pragma unroll
            for (int mi = 0; mi < 2; mi++)
                #pragma unroll
                for (int ni = 0; ni < 8; ni++)
                    mma_f16(acc[mi][ni], af[mi], bf[ni][0], bf[ni][1]);
        }

        if (more) {
            __half* Ad = As + (buf ^ 1) * GSTG;
            __half* Bd = Bs + (buf ^ 1) * GSTG;
            #pragma unroll
            for (int it = 0; it < 2; ++it) {
                *(int4*)&Ad[rowL[it] * GAS + segL[it]] = pa[it];
                *(int4*)&Bd[rowL[it] * GAS + segL[it]] = pb[it];
            }
        }
        __syncthreads();
        buf ^= 1;
    }

    // ---- fused epilogue ------------------------------------------------------
    float* S = (float*)dsm;          // 128 x SST fp32 tile (reuses mainloop smem)
    #pragma unroll
    for (int mi = 0; mi < 2; mi++) {
        int r0 = warpRow * 32 + mi * 16 + g;
        #pragma unroll
        for (int ni = 0; ni < 8; ni++) {
            int cn = warpCol * 64 + ni * 8 + tg * 2;
            *(float2*)&S[r0 * SST + cn]       = make_float2(acc[mi][ni][0], acc[mi][ni][1]);
            *(float2*)&S[(r0 + 8) * SST + cn] = make_float2(acc[mi][ni][2], acc[mi][ni][3]);
        }
    }
    __syncthreads();

    int row  = tid >> 1;
    int half = tid & 1;
    int row_g = brow + row;
    int t = row_g & (TT - 1);
    int b = row_g >> 11;                 // TT = 2048
    const float* Srow = S + row * SST;

    bool rope = (nb < 24);
    float rinv = 1.f;
    if (rope) {
        float ssq = 0.f;
        #pragma unroll
        for (int i = 0; i < 64; i += 4) {
            float4 v = *(const float4*)&Srow[half * 64 + i];
            ssq += v.x * v.x + v.y * v.y + v.z * v.z + v.w * v.w;
        }
        ssq += __shfl_xor_sync(0xffffffffu, ssq, 1);
        rinv = rsqrtf(ssq * (1.0f / 128.f) + 1e-6f);
    }

    __half* dst; int nh, hh; const float* w;
    if (nb < 16)      { dst = qt; nh = NH;  hh = nb;      w = qnw; }
    else if (nb < 24) { dst = kt; nh = NKV; hh = nb - 16; w = knw; }
    else              { dst = vt; nh = NKV; hh = nb - 24; w = qnw; }

    __half* outp = dst + ((size_t)(b * nh + hh) * TT + t) * HD + half * 64;

    if (rope) {
        float sgn = half ? 1.f : -1.f;
        #pragma unroll
        for (int i = 0; i < 64; i += 4) {
            float4 v  = *(const float4*)&Srow[half * 64 + i];
            float4 ov = *(const float4*)&Srow[(half ^ 1) * 64 + i];
            float4 cc = *(const float4*)&g_cos[t * 64 + i];
            float4 sc = *(const float4*)&g_sin[t * 64 + i];
            float4 wv = *(const float4*)&w[half * 64 + i];
            float4 wo = *(const float4*)&w[(half ^ 1) * 64 + i];
            float o0 = v.x * rinv * wv.x * cc.x + sgn * ov.x * rinv * wo.x * sc.x;
            float o1 = v.y * rinv * wv.y * cc.y + sgn * ov.y * rinv * wo.y * sc.y;
            float o2 = v.z * rinv * wv.z * cc.z + sgn * ov.z * rinv * wo.z * sc.z;
            float o3 = v.w * rinv * wv.w * cc.w + sgn * ov.w * rinv * wo.w * sc.w;
            union { __half2 h[2]; uint2 u; } pk;
            pk.h[0] = __floats2half2_rn(o0, o1);
            pk.h[1] = __floats2half2_rn(o2, o3);
            *(uint2*)&outp[i] = pk.u;
        }
    } else {
        #pragma unroll
        for (int i = 0; i < 64; i += 4) {
            float4 v = *(const float4*)&Srow[half * 64 + i];
            union { __half2 h[2]; uint2 u; } pk;
            pk.h[0] = __floats2half2_rn(v.x, v.y);
            pk.h[1] = __floats2half2_rn(v.z, v.w);
            *(uint2*)&outp[i] = pk.u;
        }
    }
}

// ---------------- fp16 tensor-core GEMM (Wo): C[M,N] fp32 = A @ B^T -----------
__global__ __launch_bounds__(256, 2) void gemm_fp16_kernel(
    const __half* __restrict__ A, const __half* __restrict__ Bm,
    float* __restrict__ C, int M, int N_, int K)
{
    __shared__ __half As[2 * GSTG];
    __shared__ __half Bs[2 * GSTG];

    int tid = threadIdx.x;
    int wid = tid >> 5, lane = tid & 31;
    int g = lane >> 2, tg = lane & 3;
    int lr = lane & 7;
    int lm = (lane >> 3) & 1;
    int lh = lane >> 4;
    int sel = lane >> 3;
    int warpRow = wid >> 1, warpCol = wid & 1;
    int brow = blockIdx.y * 128, bcol = blockIdx.x * 128;

    int rowL[2], segL[2];
    #pragma unroll
    for (int it = 0; it < 2; ++it) {
        int idx = it * 256 + tid;
        rowL[it] = idx >> 2;
        segL[it] = (idx & 3) * 8;
    }
    const __half* ApL[2];
    const __half* BpL[2];
    #pragma unroll
    for (int it = 0; it < 2; ++it) {
        ApL[it] = A  + (size_t)(brow + rowL[it]) * K + segL[it];
        BpL[it] = Bm + (size_t)(bcol + rowL[it]) * K + segL[it];
    }

    uint32_t sA = smem_u32(As), sB = smem_u32(Bs);

    float acc[2][8][4];
    #pragma unroll
    for (int mi = 0; mi < 2; mi++)
        #pragma unroll
        for (int ni = 0; ni < 8; ni++)
            #pragma unroll
            for (int c = 0; c < 4; c++) acc[mi][ni][c] = 0.f;

    #pragma unroll
    for (int it = 0; it < 2; ++it) {
        *(int4*)&As[rowL[it] * GAS + segL[it]] = *(const int4*)ApL[it];
        *(int4*)&Bs[rowL[it] * GAS + segL[it]] = *(const int4*)BpL[it];
    }
    __syncthreads();

    int buf = 0;
    for (int k0 = 0; k0 < K; k0 += 32) {
        int4 pa[2], pb[2];
        bool more = (k0 + 32 < K);
        if (more) {
            #pragma unroll
            for (int it = 0; it < 2; ++it) {
                pa[it] = *(const int4*)(ApL[it] + k0 + 32);
                pb[it] = *(const int4*)(BpL[it] + k0 + 32);
            }
        }

        uint32_t bA = sA + buf * (GSTG * 2);
        uint32_t bB = sB + buf * (GSTG * 2);
        #pragma unroll
        for (int ks = 0; ks < 2; ++ks) {
            int kk = ks * 16;
            uint32_t af[2][4];
            #pragma unroll
            for (int mi = 0; mi < 2; mi++) {
                uint32_t addr = bA + (uint32_t)(((warpRow * 32 + mi * 16 + lr + lm * 8) * GAS
                                                 + kk + lh * 8) * 2);
                LDSM_X4(af[mi][0], af[mi][1], af[mi][2], af[mi][3], addr);
            }
            uint32_t bf[8][2];
            #pragma unroll
            for (int nb = 0; nb < 4; nb++) {
                int n0 = warpCol * 64 + nb * 16;
                uint32_t addr = bB + (uint32_t)(((n0 + lr + (sel >> 1) * 8) * GAS
                                                 + kk + (sel & 1) * 8) * 2);
                LDSM_X4(bf[2 * nb][0], bf[2 * nb][1], bf[2 * nb + 1][0], bf[2 * nb + 1][1], addr);
            }
            #pragma unroll
            for (int mi = 0; mi < 2; mi++)
                #pragma unroll
                for (int ni = 0; ni < 8; ni++)
                    mma_f16(acc[mi][ni], af[mi], bf[ni][0], bf[ni][1]);
        }

        if (more) {
            __half* Ad = As + (buf ^ 1) * GSTG;
            __half* Bd = Bs + (buf ^ 1) * GSTG;
            #pragma unroll
            for (int it = 0; it < 2; ++it) {
                *(int4*)&Ad[rowL[it] * GAS + segL[it]] = pa[it];
                *(int4*)&Bd[rowL[it] * GAS + segL[it]] = pb[it];
            }
        }
        __syncthreads();
        buf ^= 1;
    }

    #pragma unroll
    for (int mi = 0; mi < 2; mi++) {
        int r0 = brow + warpRow * 32 + mi * 16 + g;
        #pragma unroll
        for (int ni = 0; ni < 8; ni++) {
            int cn = bcol + warpCol * 64 + ni * 8 + tg * 2;
            *(float2*)(C + (size_t)r0 * N_ + cn) = make_float2(acc[mi][ni][0], acc[mi][ni][1]);
            *(float2*)(C + (size_t)(r0 + 8) * N_ + cn) = make_float2(acc[mi][ni][2], acc[mi][ni][3]);
        }
    }
}

// ------------- Causal flash attention: fp16 mma, cp.async K/V pipeline --------
#define US_STR 136   // halves; 272B rows -> ldmatrix conflict-free
#define PS_STR 72
#define FL_KV  (64 * US_STR)
#define FL_U   (128 * US_STR)
#define FLASH_SMEM ((2 * FL_KV + FL_U) * 2)

__global__ __launch_bounds__(256) void flash_fp16_kernel(
    const __half* __restrict__ Q, const __half* __restrict__ Kt,
    const __half* __restrict__ Vt, __half* __restrict__ ctx)
{
    extern __shared__ __half smh[];
    __half* Ks = smh;
    __half* Vs = smh + FL_KV;
    __half* Us = smh + 2 * FL_KV;
    __half* Ps = Us;

    int tid = threadIdx.x;
    int wid = tid >> 5, lane = tid & 31;
    int g = lane >> 2, tg = lane & 3;
    int lr = lane & 7;
    int lm = (lane >> 3) & 1;
    int lh = lane >> 4;
    int p8 = (lane >> 3) & 1;
    int p16 = lane >> 4;

    int hw = wid >> 2;
    int w4 = wid & 3;
    int base = w4 * 16;

    int qb = blockIdx.x;
    int bk = blockIdx.y;
    int b = bk / NKV, kvh = bk % NKV;
    int h = kvh * 2 + hw;

    const __half* Kbase = Kt + ((size_t)(b * NKV + kvh) * TT) * HD;
    const __half* Vbase = Vt + ((size_t)(b * NKV + kvh) * TT) * HD;

    uint32_t sK = smem_u32(Ks), sV = smem_u32(Vs), sU = smem_u32(Us), sP = sU;

    int cprow[4], cpc8[4];
    uint32_t cpK[4], cpV[4];
    #pragma unroll
    for (int it = 0; it < 4; ++it) {
        int idx = it * 256 + tid;
        cprow[it] = idx >> 4;
        cpc8[it]  = (idx & 15) * 8;
        cpK[it] = sK + (uint32_t)((cprow[it] * US_STR + cpc8[it]) * 2);
        cpV[it] = sV + (uint32_t)((cprow[it] * US_STR + cpc8[it]) * 2);
    }

    #pragma unroll
    for (int it = 0; it < 4; ++it)
        CP_ASYNC16(cpK[it], Kbase + (size_t)cprow[it] * HD + cpc8[it]);
    CP_COMMIT();
    #pragma unroll
    for (int it = 0; it < 4; ++it)
        CP_ASYNC16(cpV[it], Vbase + (size_t)cprow[it] * HD + cpc8[it]);
    CP_COMMIT();

    {
        const __half* Qh = Q + ((size_t)(b * NH + kvh * 2 + hw) * TT + qb * 64) * HD;
        int t128 = tid & 127;
        #pragma unroll
        for (int it = 0; it < 8; ++it) {
            int idx = it * 128 + t128;
            int r = idx >> 4;
            int c8 = (idx & 15) * 8;
            *(int4*)&Us[(hw * 64 + r) * US_STR + c8] =
                *(const int4*)(Qh + (size_t)r * HD + c8);
        }
    }
    __syncthreads();

    uint32_t qa[8][4];
    #pragma unroll
    for (int ks = 0; ks < 8; ++ks) {
        uint32_t au = sU + (uint32_t)(((hw * 64 + base + lr + lm * 8) * US_STR + ks * 16 + lh * 8) * 2);
        LDSM_X4(qa[ks][0], qa[ks][1], qa[ks][2], qa[ks][3], au);
    }

    float o[16][4];
    #pragma unroll
    for (int ni = 0; ni < 16; ni++)
        #pragma unroll
        for (int c = 0; c < 4; c++) o[ni][c] = 0.f;
    float mrow[2] = {-1e30f, -1e30f};
    float lrow[2] = {0.f, 0.f};

    const float scale = 0.08838834764831845f;   // 128^-0.5
    const float L2E = 1.44269504088896f;

    for (int kb = 0; kb <= qb; ++kb) {
        bool more = (kb < qb);
        CP_WAIT1();
        __syncthreads();

        float s[8][4];
        #pragma unroll
        for (int ni = 0; ni < 8; ni++)
            #pragma unroll
            for (int c = 0; c < 4; c++) s[ni][c] = 0.f;

        #pragma unroll
        for (int ks = 0; ks < 8; ++ks) {
            int kk = ks * 16;
            #pragma unroll
            for (int np = 0; np < 4; np++) {
                uint32_t r0, r1, r2, r3;
                uint32_t ak = sK + (uint32_t)(((np * 16 + p16 * 8 + lr) * US_STR
                                               + kk + p8 * 8) * 2);
                LDSM_X4(r0, r1, r2, r3, ak);
                mma_f16(s[2 * np],     qa[ks], r0, r1);
                mma_f16(s[2 * np + 1], qa[ks], r2, r3);
            }
        }
        __syncthreads();

        if (more) {
            const __half* Kn = Kbase + (size_t)(kb + 1) * 64 * HD;
            #pragma unroll
            for (int it = 0; it < 4; ++it)
                CP_ASYNC16(cpK[it], Kn + (size_t)cprow[it] * HD + cpc8[it]);
        }
        CP_COMMIT();

        bool diag = (kb == qb);
        int rowA = base + g;
        int rowB = rowA + 8;
        float mA = -1e30f, mB = -1e30f;
        #pragma unroll
        for (int ni = 0; ni < 8; ni++) {
            #pragma unroll
            for (int c = 0; c < 4; c++) {
                float sv = s[ni][c] * scale;
                if (diag) {
                    int kcol = ni * 8 + tg * 2 + (c & 1);
                    int qrow = (c < 2) ? rowA : rowB;
                    if (kcol > qrow) sv = -1e30f;
                }
                s[ni][c] = sv;
            }
            mA = fmaxf(mA, fmaxf(s[ni][0], s[ni][1]));
            mB = fmaxf(mB, fmaxf(s[ni][2], s[ni][3]));
        }
        #pragma unroll
        for (int off = 1; off < 4; off <<= 1) {
            mA = fmaxf(mA, __shfl_xor_sync(0xffffffffu, mA, off));
            mB = fmaxf(mB, __shfl_xor_sync(0xffffffffu, mB, off));
        }
        float mnA = fmaxf(mrow[0], mA);
        float mnB = fmaxf(mrow[1], mB);
        float alA = exp2f((mrow[0] - mnA) * L2E);
        float alB = exp2f((mrow[1] - mnB) * L2E);
        mrow[0] = mnA; mrow[1] = mnB;

        float lA = 0.f, lB = 0.f;
        #pragma unroll
        for (int ni = 0; ni < 8; ni++) {
            s[ni][0] = exp2f((s[ni][0] - mnA) * L2E);
            s[ni][1] = exp2f((s[ni][1] - mnA) * L2E);
            s[ni][2] = exp2f((s[ni][2] - mnB) * L2E);
            s[ni][3] = exp2f((s[ni][3] - mnB) * L2E);
            lA += s[ni][0] + s[ni][1];
            lB += s[ni][2] + s[ni][3];
        }
        #pragma unroll
        for (int off = 1; off < 4; off <<= 1) {
            lA += __shfl_xor_sync(0xffffffffu, lA, off);
            lB += __shfl_xor_sync(0xffffffffu, lB, off);
        }
        lrow[0] = lrow[0] * alA + lA;
        lrow[1] = lrow[1] * alB + lB;
        #pragma unroll
        for (int ni = 0; ni < 16; ni++) {
            o[ni][0] *= alA; o[ni][1] *= alA;
            o[ni][2] *= alB; o[ni][3] *= alB;
        }

        int prowA = hw * 64 + rowA;
        int prowB = hw * 64 + rowB;
        #pragma unroll
        for (int ni = 0; ni < 8; ni++) {
            int cn = ni * 8 + tg * 2;
            *(__half2*)&Ps[prowA * PS_STR + cn] = __floats2half2_rn(s[ni][0], s[ni][1]);
            *(__half2*)&Ps[prowB * PS_STR + cn] = __floats2half2_rn(s[ni][2], s[ni][3]);
        }
        __syncwarp();

        CP_WAIT1();
        __syncthreads();

        #pragma unroll
        for (int ks = 0; ks < 4; ++ks) {
            int kk = ks * 16;
            uint32_t pa4[4];
            uint32_t ap = sP + (uint32_t)(((hw * 64 + base + lr + lm * 8) * PS_STR + kk + lh * 8) * 2);
            LDSM_X4(pa4[0], pa4[1], pa4[2], pa4[3], ap);
            #pragma unroll
            for (int np = 0; np < 8; np++) {
                uint32_t r0, r1, r2, r3;
                uint32_t av = sV + (uint32_t)(((kk + p8 * 8 + lr) * US_STR
                                               + np * 16 + p16 * 8) * 2);
                LDSM_X4T(r0, r1, r2, r3, av);
                mma_f16(o[2 * np],     pa4, r0, r1);
                mma_f16(o[2 * np + 1], pa4, r2, r3);
            }
        }
        __syncthreads();

        if (more) {
            const __half* Vn = Vbase + (size_t)(kb + 1) * 64 * HD;
            #pragma unroll
            for (int it = 0; it < 4; ++it)
                CP_ASYNC16(cpV[it], Vn + (size_t)cprow[it] * HD + cpc8[it]);
        }
        CP_COMMIT();
    }

    float ivA = 1.0f / lrow[0];
    float ivB = 1.0f / lrow[1];
    int qA = qb * 64 + base + g;
    int qB = qA + 8;
    size_t offA = (size_t)(b * TT + qA) * (NH * HD) + h * HD;
    size_t offB = (size_t)(b * TT + qB) * (NH * HD) + h * HD;
    #pragma unroll
    for (int ni = 0; ni < 16; ni++) {
        int dn = ni * 8 + tg * 2;
        *(__half2*)(ctx + offA + dn) = __floats2half2_rn(o[ni][0] * ivA, o[ni][1] * ivA);
        *(__half2*)(ctx + offB + dn) = __floats2half2_rn(o[ni][2] * ivB, o[ni][3] * ivB);
    }
}

// ---------------------------- launch -----------------------------------------
extern "C" void kernel_launch(void* const* d_in, const int* in_sizes, int n_in,
                              void* d_out, int out_size)
{
    const float* x    = (const float*)d_in[0];
    // d_in[1] = attn_mask (pure causal; applied analytically)
    const float* Wq   = (const float*)d_in[2];
    const float* Wk   = (const float*)d_in[3];
    const float* Wv   = (const float*)d_in[4];
    const float* Wo   = (const float*)d_in[5];
    const float* qnw  = (const float*)d_in[6];
    const float* knw  = (const float*)d_in[7];
    float* out = (float*)d_out;

    __half *qt, *kt, *vt, *xh, *wqkv, *wo, *ctx;
    cudaGetSymbolAddress((void**)&qt,   g_qt);
    cudaGetSymbolAddress((void**)&kt,   g_kt);
    cudaGetSymbolAddress((void**)&vt,   g_vt);
    cudaGetSymbolAddress((void**)&xh,   g_xh);
    cudaGetSymbolAddress((void**)&wqkv, g_wqkv);
    cudaGetSymbolAddress((void**)&wo,   g_wo);
    cudaGetSymbolAddress((void**)&ctx,  g_ctx);

    cudaFuncSetAttribute(flash_fp16_kernel, cudaFuncAttributeMaxDynamicSharedMemorySize,
                         FLASH_SMEM);
    cudaFuncSetAttribute(gemm_qkv_kernel, cudaFuncAttributeMaxDynamicSharedMemorySize,
                         QKV_SMEM);

    // 0: rope table
    rope_table_kernel<<<TT / 2, 128>>>();
    // 1: x -> fp16
    conv_half_kernel<<<(unsigned)(((size_t)MM * HH / 4 + 255) / 256), 256>>>(
        x, xh, (size_t)MM * HH);
    // 2-5: W^T fp16 (QKV into one buffer, Wo)
    wt_half_kernel<<<dim3(2048 / 32, 2048 / 32), 256>>>(Wq, wqkv, 2048, 2048);
    wt_half_kernel<<<dim3(1024 / 32, 2048 / 32), 256>>>(Wk, wqkv + (size_t)2048 * 2048, 2048, 1024);
    wt_half_kernel<<<dim3(1024 / 32, 2048 / 32), 256>>>(Wv, wqkv + (size_t)3072 * 2048, 2048, 1024);
    wt_half_kernel<<<dim3(2048 / 32, 2048 / 32), 256>>>(Wo, wo, 2048, 2048);
    // 6: fused QKV projection + RMSNorm + RoPE + transpose -> qt/kt/vt fp16
    gemm_qkv_kernel<<<dim3(32, MM / 128), 256, QKV_SMEM>>>(
        xh, wqkv, qt, kt, vt, qnw, knw);
    // 7: flash attention (fp16 mma, 2 GQA heads/CTA, cp.async pipeline)
    flash_fp16_kernel<<<dim3(TT / 64, BB * NKV), 256, FLASH_SMEM>>>(qt, kt, vt, ctx);
    // 8: output projection
    gemm_fp16_kernel<<<dim3(2048 / 128, MM / 128), 256>>>(ctx, wo, out, MM, 2048, HH);
}

// round 11
// speedup vs baseline: 1.0459x; 1.0459x over previous
#include <cuda_runtime.h>
#include <cuda_fp16.h>
#include <cstdint>
#include <cstddef>
#include <math.h>

// Problem constants
#define BB   2
#define TT   2048
#define HH   2048
#define NH   16
#define NKV  8
#define HD   128
#define MM   (BB*TT)            // 4096 rows

// ---------------- scratch (static device globals; no allocation) -------------
__device__ float g_qkvraw[(size_t)MM * 4096];      // [b*T+t, {Q|K|V}]
__device__ __half g_qt[(size_t)BB * NH * TT * HD]; // [b,h,t,d] fp16
__device__ __half g_kt[(size_t)BB * NKV * TT * HD];
__device__ __half g_vt[(size_t)BB * NKV * TT * HD];
__device__ __half g_xh[(size_t)MM * HH];           // x fp16
__device__ __half g_wqkv[(size_t)4096 * 2048];     // [N=4096, K=2048] fp16 (Q|K|V rows)
__device__ __half g_wo[(size_t)2048 * 2048];       // Wo^T [N,K] fp16
__device__ __half g_ctx[(size_t)MM * HH];          // [b*T+t, h*HD+d] fp16
__device__ float g_cos[TT * 64];
__device__ float g_sin[TT * 64];

// ---------------- helpers ----------------------------------------------------
__device__ __forceinline__ uint32_t smem_u32(const void* p) {
    uint32_t a;
    asm("{ .reg .u64 t; cvta.to.shared.u64 t, %1; cvt.u32.u64 %0, t; }" : "=r"(a) : "l"(p));
    return a;
}

__device__ __forceinline__ void mma_f16(float c[4], const uint32_t a[4],
                                        uint32_t b0, uint32_t b1) {
    asm volatile(
        "mma.sync.aligned.m16n8k16.row.col.f32.f16.f16.f32 "
        "{%0,%1,%2,%3}, {%4,%5,%6,%7}, {%8,%9}, {%0,%1,%2,%3};\n"
        : "+f"(c[0]), "+f"(c[1]), "+f"(c[2]), "+f"(c[3])
        : "r"(a[0]), "r"(a[1]), "r"(a[2]), "r"(a[3]), "r"(b0), "r"(b1));
}

#define LDSM_X4(R0,R1,R2,R3,ADDR)                                              \
    asm volatile("ldmatrix.sync.aligned.m8n8.x4.shared.b16 {%0,%1,%2,%3}, [%4];" \
        : "=r"(R0), "=r"(R1), "=r"(R2), "=r"(R3) : "r"(ADDR))
#define LDSM_X4T(R0,R1,R2,R3,ADDR)                                             \
    asm volatile("ldmatrix.sync.aligned.m8n8.x4.trans.shared.b16 {%0,%1,%2,%3}, [%4];" \
        : "=r"(R0), "=r"(R1), "=r"(R2), "=r"(R3) : "r"(ADDR))

#define CP_ASYNC16(SMEM, GPTR) \
    asm volatile("cp.async.cg.shared.global [%0], [%1], 16;" :: "r"(SMEM), "l"(GPTR) : "memory")
#define CP_COMMIT() asm volatile("cp.async.commit_group;" ::: "memory")
#define CP_WAIT1()  asm volatile("cp.async.wait_group 1;" ::: "memory")
#define CP_WAIT0()  asm volatile("cp.async.wait_group 0;" ::: "memory")

// ---------------- RoPE tables (fp64 angle, fp32 trig after reduction) ---------
__global__ void rope_table_kernel() {
    int t = blockIdx.x * 2 + (threadIdx.x >> 6);
    int j = threadIdx.x & 63;  // 0..63
    double inv = exp(-(double)j * (13.815510557964274 / 64.0)); // theta=1e6
    double ang = (double)t * inv;
    const double TWO_PI = 6.283185307179586476925286766559;
    double red = ang - TWO_PI * floor(ang * (1.0 / TWO_PI));
    float c, s;
    sincosf((float)red, &s, &c);
    g_cos[t * 64 + j] = c;
    g_sin[t * 64 + j] = s;
}

// ---------------- fp32 -> fp16 convert ----------------------------------------
__global__ __launch_bounds__(256) void conv_half_kernel(
    const float* __restrict__ in, __half* __restrict__ out, size_t n)
{
    size_t i = ((size_t)blockIdx.x * 256 + threadIdx.x) * 4;
    if (i < n) {
        float4 v = *(const float4*)(in + i);
        *(__half2*)(out + i)     = __floats2half2_rn(v.x, v.y);
        *(__half2*)(out + i + 2) = __floats2half2_rn(v.z, v.w);
    }
}

// ---------------- W [K,N] fp32 -> Wt [N,K] fp16 -------------------------------
__global__ __launch_bounds__(256) void wt_half_kernel(
    const float* __restrict__ W, __half* __restrict__ Wt, int K, int N_)
{
    __shared__ float t[32][33];
    int n0 = blockIdx.x * 32, k0 = blockIdx.y * 32;
    int tx = threadIdx.x & 31, ty = threadIdx.x >> 5;   // 32 x 8
    #pragma unroll
    for (int i = 0; i < 32; i += 8)
        t[ty + i][tx] = W[(size_t)(k0 + ty + i) * N_ + n0 + tx];
    __syncthreads();
    #pragma unroll
    for (int i = 0; i < 32; i += 8)
        Wt[(size_t)(n0 + ty + i) * K + k0 + tx] = __float2half(t[tx][ty + i]);
}

// ---------------- fp16 tensor-core GEMM: C[M,N] = A[M,K] @ B[N,K]^T -----------
// BK=32, double-buffered smem, ldmatrix fragment loads.
#define GAS 40   // smem row stride in halves (80B = 5x16B, odd -> ldmatrix clean)
#define GSTG (128 * GAS)
__global__ __launch_bounds__(256, 2) void gemm_fp16_kernel(
    const __half* __restrict__ A, const __half* __restrict__ Bm,
    float* __restrict__ C, int M, int N_, int K)
{
    __shared__ __half As[2 * GSTG];
    __shared__ __half Bs[2 * GSTG];

    int tid = threadIdx.x;
    int wid = tid >> 5, lane = tid & 31;
    int g = lane >> 2, tg = lane & 3;
    int lr = lane & 7;
    int lm = (lane >> 3) & 1;
    int lh = lane >> 4;
    int sel = lane >> 3;
    int warpRow = wid >> 1, warpCol = wid & 1;  // 4 x 2 warps
    int brow = blockIdx.y * 128, bcol = blockIdx.x * 128;

    int rowL[2], segL[2];
    #pragma unroll
    for (int it = 0; it < 2; ++it) {
        int idx = it * 256 + tid;
        rowL[it] = idx >> 2;
        segL[it] = (idx & 3) * 8;
    }
    const __half* ApL[2];
    const __half* BpL[2];
    #pragma unroll
    for (int it = 0; it < 2; ++it) {
        ApL[it] = A  + (size_t)(brow + rowL[it]) * K + segL[it];
        BpL[it] = Bm + (size_t)(bcol + rowL[it]) * K + segL[it];
    }

    uint32_t sA = smem_u32(As), sB = smem_u32(Bs);

    float acc[2][8][4];
    #pragma unroll
    for (int mi = 0; mi < 2; mi++)
        #pragma unroll
        for (int ni = 0; ni < 8; ni++)
            #pragma unroll
            for (int c = 0; c < 4; c++) acc[mi][ni][c] = 0.f;

    #pragma unroll
    for (int it = 0; it < 2; ++it) {
        *(int4*)&As[rowL[it] * GAS + segL[it]] = *(const int4*)ApL[it];
        *(int4*)&Bs[rowL[it] * GAS + segL[it]] = *(const int4*)BpL[it];
    }
    __syncthreads();

    int buf = 0;
    for (int k0 = 0; k0 < K; k0 += 32) {
        int4 pa[2], pb[2];
        bool more = (k0 + 32 < K);
        if (more) {
            #pragma unroll
            for (int it = 0; it < 2; ++it) {
                pa[it] = *(const int4*)(ApL[it] + k0 + 32);
                pb[it] = *(const int4*)(BpL[it] + k0 + 32);
            }
        }

        uint32_t bA = sA + buf * (GSTG * 2);
        uint32_t bB = sB + buf * (GSTG * 2);
        #pragma unroll
        for (int ks = 0; ks < 2; ++ks) {
            int kk = ks * 16;
            uint32_t af[2][4];
            #pragma unroll
            for (int mi = 0; mi < 2; mi++) {
                uint32_t addr = bA + (uint32_t)(((warpRow * 32 + mi * 16 + lr + lm * 8) * GAS
                                                 + kk + lh * 8) * 2);
                LDSM_X4(af[mi][0], af[mi][1], af[mi][2], af[mi][3], addr);
            }
            uint32_t bf[8][2];
            #pragma unroll
            for (int nb = 0; nb < 4; nb++) {
                int n0 = warpCol * 64 + nb * 16;
                uint32_t addr = bB + (uint32_t)(((n0 + lr + (sel >> 1) * 8) * GAS
                                                 + kk + (sel & 1) * 8) * 2);
                LDSM_X4(bf[2 * nb][0], bf[2 * nb][1], bf[2 * nb + 1][0], bf[2 * nb + 1][1], addr);
            }
            #pragma unroll
            for (int mi = 0; mi < 2; mi++)
                #pragma unroll
                for (int ni = 0; ni < 8; ni++)
                    mma_f16(acc[mi][ni], af[mi], bf[ni][0], bf[ni][1]);
        }

        if (more) {
            __half* Ad = As + (buf ^ 1) * GSTG;
            __half* Bd = Bs + (buf ^ 1) * GSTG;
            #pragma unroll
            for (int it = 0; it < 2; ++it) {
                *(int4*)&Ad[rowL[it] * GAS + segL[it]] = pa[it];
                *(int4*)&Bd[rowL[it] * GAS + segL[it]] = pb[it];
            }
        }
        __syncthreads();
        buf ^= 1;
    }

    #pragma unroll
    for (int mi = 0; mi < 2; mi++) {
        int r0 = brow + warpRow * 32 + mi * 16 + g;
        #pragma unroll
        for (int ni = 0; ni < 8; ni++) {
            int cn = bcol + warpCol * 64 + ni * 8 + tg * 2;
            *(float2*)(C + (size_t)r0 * N_ + cn) = make_float2(acc[mi][ni][0], acc[mi][ni][1]);
            *(float2*)(C + (size_t)(r0 + 8) * N_ + cn) = make_float2(acc[mi][ni][2], acc[mi][ni][3]);
        }
    }
}

// ------------- RMSNorm + RoPE + transpose -> [b,h,t,d] fp16 -------------------
__global__ __launch_bounds__(128) void norm_rope_kernel(
    const float* __restrict__ src, __half* __restrict__ dst,
    const float* __restrict__ w, int nheads, int srcStride)
{
    int r = blockIdx.x;              // (b*T+t)*nheads + h
    int d = threadIdx.x;             // 0..127
    int h  = r % nheads;
    int bt = r / nheads;
    int t  = bt % TT;
    int b  = bt / TT;

    float val = src[(size_t)bt * srcStride + h * HD + d];
    __shared__ float red[4];
    __shared__ float sh[HD];

    float ss = val * val;
    #pragma unroll
    for (int off = 16; off; off >>= 1)
        ss += __shfl_xor_sync(0xffffffffu, ss, off);
    if ((d & 31) == 0) red[d >> 5] = ss;
    __syncthreads();
    float tot = red[0] + red[1] + red[2] + red[3];
    float nv = val * rsqrtf(tot * (1.0f / HD) + 1e-6f) * w[d];
    sh[d] = nv;
    __syncthreads();

    int j = d & 63;
    float c = g_cos[t * 64 + j];
    float s = g_sin[t * 64 + j];
    float other = (d < 64) ? -sh[d + 64] : sh[d - 64];
    float out = nv * c + other * s;

    dst[((size_t)(b * nheads + h) * TT + t) * HD + d] = __float2half(out);
}

// ------------- V transpose -> [b,h,t,d] fp16 ----------------------------------
__global__ __launch_bounds__(128) void transpose_kernel(
    const float* __restrict__ src, __half* __restrict__ dst, int nheads, int srcStride)
{
    int r = blockIdx.x;
    int d = threadIdx.x;
    int h  = r % nheads;
    int bt = r / nheads;
    int t  = bt % TT;
    int b  = bt / TT;
    dst[((size_t)(b * nheads + h) * TT + t) * HD + d] =
        __float2half(src[(size_t)bt * srcStride + h * HD + d]);
}

// ------------- Causal flash attention: fp16 mma, cp.async pipeline ------------
// Paired Q-tiles per CTA: phase 0 -> qb = x, phase 1 -> qb = 31-x; every CTA
// does exactly 33 tile-iterations (perfect balance). 2 GQA heads per CTA.
#define US_STR 136   // halves; 272B rows -> ldmatrix conflict-free
#define PS_STR 72
#define FL_KV  (64 * US_STR)
#define FL_U   (128 * US_STR)
#define FLASH_SMEM ((2 * FL_KV + FL_U) * 2)
#define NQB    (TT / 64)         // 32 q-blocks

__global__ __launch_bounds__(256) void flash_fp16_kernel(
    const __half* __restrict__ Q, const __half* __restrict__ Kt,
    const __half* __restrict__ Vt, __half* __restrict__ ctx)
{
    extern __shared__ __half smh[];
    __half* Ks = smh;
    __half* Vs = smh + FL_KV;
    __half* Us = smh + 2 * FL_KV;
    __half* Ps = Us;

    int tid = threadIdx.x;
    int wid = tid >> 5, lane = tid & 31;
    int g = lane >> 2, tg = lane & 3;
    int lr = lane & 7;
    int lm = (lane >> 3) & 1;
    int lh = lane >> 4;
    int p8 = (lane >> 3) & 1;
    int p16 = lane >> 4;

    int hw = wid >> 2;
    int w4 = wid & 3;
    int base = w4 * 16;

    int qbx = blockIdx.x;            // 0..15
    int bk = blockIdx.y;
    int b = bk / NKV, kvh = bk % NKV;
    int h = kvh * 2 + hw;

    const __half* Kbase = Kt + ((size_t)(b * NKV + kvh) * TT) * HD;
    const __half* Vbase = Vt + ((size_t)(b * NKV + kvh) * TT) * HD;

    uint32_t sK = smem_u32(Ks), sV = smem_u32(Vs), sU = smem_u32(Us), sP = sU;

    int cprow[4], cpc8[4];
    uint32_t cpK[4], cpV[4];
    #pragma unroll
    for (int it = 0; it < 4; ++it) {
        int idx = it * 256 + tid;
        cprow[it] = idx >> 4;
        cpc8[it]  = (idx & 15) * 8;
        cpK[it] = sK + (uint32_t)((cprow[it] * US_STR + cpc8[it]) * 2);
        cpV[it] = sV + (uint32_t)((cprow[it] * US_STR + cpc8[it]) * 2);
    }

    const float scale = 0.08838834764831845f;   // 128^-0.5
    const float L2E = 1.44269504088896f;

    for (int ph = 0; ph < 2; ++ph) {
        int qb = ph ? (NQB - 1 - qbx) : qbx;

        // drain pipeline; all prior reads/writes of Ks/Vs/Us complete
        CP_WAIT0();
        __syncthreads();

        // prefetch K0, V0 for this phase
        #pragma unroll
        for (int it = 0; it < 4; ++it)
            CP_ASYNC16(cpK[it], Kbase + (size_t)cprow[it] * HD + cpc8[it]);
        CP_COMMIT();
        #pragma unroll
        for (int it = 0; it < 4; ++it)
            CP_ASYNC16(cpV[it], Vbase + (size_t)cprow[it] * HD + cpc8[it]);
        CP_COMMIT();

        // stage Q for this qb (each head-half loads its own tile)
        {
            const __half* Qh = Q + ((size_t)(b * NH + kvh * 2 + hw) * TT + qb * 64) * HD;
            int t128 = tid & 127;
            #pragma unroll
            for (int it = 0; it < 8; ++it) {
                int idx = it * 128 + t128;
                int r = idx >> 4;
                int c8 = (idx & 15) * 8;
                *(int4*)&Us[(hw * 64 + r) * US_STR + c8] =
                    *(const int4*)(Qh + (size_t)r * HD + c8);
            }
        }
        __syncthreads();

        uint32_t qa[8][4];
        #pragma unroll
        for (int ks = 0; ks < 8; ++ks) {
            uint32_t au = sU + (uint32_t)(((hw * 64 + base + lr + lm * 8) * US_STR + ks * 16 + lh * 8) * 2);
            LDSM_X4(qa[ks][0], qa[ks][1], qa[ks][2], qa[ks][3], au);
        }

        float o[16][4];
        #pragma unroll
        for (int ni = 0; ni < 16; ni++)
            #pragma unroll
            for (int c = 0; c < 4; c++) o[ni][c] = 0.f;
        float mrow[2] = {-1e30f, -1e30f};
        float lrow[2] = {0.f, 0.f};

        for (int kb = 0; kb <= qb; ++kb) {
            bool more = (kb < qb);
            CP_WAIT1();
            __syncthreads();

            float s[8][4];
            #pragma unroll
            for (int ni = 0; ni < 8; ni++)
                #pragma unroll
                for (int c = 0; c < 4; c++) s[ni][c] = 0.f;

            #pragma unroll
            for (int ks = 0; ks < 8; ++ks) {
                int kk = ks * 16;
                #pragma unroll
                for (int np = 0; np < 4; np++) {
                    uint32_t r0, r1, r2, r3;
                    uint32_t ak = sK + (uint32_t)(((np * 16 + p16 * 8 + lr) * US_STR
                                                   + kk + p8 * 8) * 2);
                    LDSM_X4(r0, r1, r2, r3, ak);
                    mma_f16(s[2 * np],     qa[ks], r0, r1);
                    mma_f16(s[2 * np + 1], qa[ks], r2, r3);
                }
            }
            __syncthreads();

            if (more) {
                const __half* Kn = Kbase + (size_t)(kb + 1) * 64 * HD;
                #pragma unroll
                for (int it = 0; it < 4; ++it)
                    CP_ASYNC16(cpK[it], Kn + (size_t)cprow[it] * HD + cpc8[it]);
            }
            CP_COMMIT();

            bool diag = (kb == qb);
            int rowA = base + g;
            int rowB = rowA + 8;
            float mA = -1e30f, mB = -1e30f;
            #pragma unroll
            for (int ni = 0; ni < 8; ni++) {
                #pragma unroll
                for (int c = 0; c < 4; c++) {
                    float sv = s[ni][c] * scale;
                    if (diag) {
                        int kcol = ni * 8 + tg * 2 + (c & 1);
                        int qrow = (c < 2) ? rowA : rowB;
                        if (kcol > qrow) sv = -1e30f;
                    }
                    s[ni][c] = sv;
                }
                mA = fmaxf(mA, fmaxf(s[ni][0], s[ni][1]));
                mB = fmaxf(mB, fmaxf(s[ni][2], s[ni][3]));
            }
            #pragma unroll
            for (int off = 1; off < 4; off <<= 1) {
                mA = fmaxf(mA, __shfl_xor_sync(0xffffffffu, mA, off));
                mB = fmaxf(mB, __shfl_xor_sync(0xffffffffu, mB, off));
            }
            float mnA = fmaxf(mrow[0], mA);
            float mnB = fmaxf(mrow[1], mB);
            float alA = exp2f((mrow[0] - mnA) * L2E);
            float alB = exp2f((mrow[1] - mnB) * L2E);
            mrow[0] = mnA; mrow[1] = mnB;

            float lA = 0.f, lB = 0.f;
            #pragma unroll
            for (int ni = 0; ni < 8; ni++) {
                s[ni][0] = exp2f((s[ni][0] - mnA) * L2E);
                s[ni][1] = exp2f((s[ni][1] - mnA) * L2E);
                s[ni][2] = exp2f((s[ni][2] - mnB) * L2E);
                s[ni][3] = exp2f((s[ni][3] - mnB) * L2E);
                lA += s[ni][0] + s[ni][1];
                lB += s[ni][2] + s[ni][3];
            }
            #pragma unroll
            for (int off = 1; off < 4; off <<= 1) {
                lA += __shfl_xor_sync(0xffffffffu, lA, off);
                lB += __shfl_xor_sync(0xffffffffu, lB, off);
            }
            lrow[0] = lrow[0] * alA + lA;
            lrow[1] = lrow[1] * alB + lB;
            #pragma unroll
            for (int ni = 0; ni < 16; ni++) {
                o[ni][0] *= alA; o[ni][1] *= alA;
                o[ni][2] *= alB; o[ni][3] *= alB;
            }

            int prowA = hw * 64 + rowA;
            int prowB = hw * 64 + rowB;
            #pragma unroll
            for (int ni = 0; ni < 8; ni++) {
                int cn = ni * 8 + tg * 2;
                *(__half2*)&Ps[prowA * PS_STR + cn] = __floats2half2_rn(s[ni][0], s[ni][1]);
                *(__half2*)&Ps[prowB * PS_STR + cn] = __floats2half2_rn(s[ni][2], s[ni][3]);
            }
            __syncwarp();

            CP_WAIT1();
            __syncthreads();

            #pragma unroll
            for (int ks = 0; ks < 4; ++ks) {
                int kk = ks * 16;
                uint32_t pa4[4];
                uint32_t ap = sP + (uint32_t)(((hw * 64 + base + lr + lm * 8) * PS_STR + kk + lh * 8) * 2);
                LDSM_X4(pa4[0], pa4[1], pa4[2], pa4[3], ap);
                #pragma unroll
                for (int np = 0; np < 8; np++) {
                    uint32_t r0, r1, r2, r3;
                    uint32_t av = sV + (uint32_t)(((kk + p8 * 8 + lr) * US_STR
                                                   + np * 16 + p16 * 8) * 2);
                    LDSM_X4T(r0, r1, r2, r3, av);
                    mma_f16(o[2 * np],     pa4, r0, r1);
                    mma_f16(o[2 * np + 1], pa4, r2, r3);
                }
            }
            __syncthreads();

            if (more) {
                const __half* Vn = Vbase + (size_t)(kb + 1) * 64 * HD;
                #pragma unroll
                for (int it = 0; it < 4; ++it)
                    CP_ASYNC16(cpV[it], Vn + (size_t)cprow[it] * HD + cpc8[it]);
            }
            CP_COMMIT();
        }

        // epilogue for this phase
        float ivA = 1.0f / lrow[0];
        float ivB = 1.0f / lrow[1];
        int qA = qb * 64 + base + g;
        int qB = qA + 8;
        size_t offA = (size_t)(b * TT + qA) * (NH * HD) + h * HD;
        size_t offB = (size_t)(b * TT + qB) * (NH * HD) + h * HD;
        #pragma unroll
        for (int ni = 0; ni < 16; ni++) {
            int dn = ni * 8 + tg * 2;
            *(__half2*)(ctx + offA + dn) = __floats2half2_rn(o[ni][0] * ivA, o[ni][1] * ivA);
            *(__half2*)(ctx + offB + dn) = __floats2half2_rn(o[ni][2] * ivB, o[ni][3] * ivB);
        }
    }
}

// ---------------------------- launch -----------------------------------------
extern "C" void kernel_launch(void* const* d_in, const int* in_sizes, int n_in,
                              void* d_out, int out_size)
{
    const float* x    = (const float*)d_in[0];
    // d_in[1] = attn_mask (pure causal; applied analytically)
    const float* Wq   = (const float*)d_in[2];
    const float* Wk   = (const float*)d_in[3];
    const float* Wv   = (const float*)d_in[4];
    const float* Wo   = (const float*)d_in[5];
    const float* qnw  = (const float*)d_in[6];
    const float* knw  = (const float*)d_in[7];
    float* out = (float*)d_out;

    float *qkvraw;
    __half *qt, *kt, *vt, *xh, *wqkv, *wo, *ctx;
    cudaGetSymbolAddress((void**)&qkvraw, g_qkvraw);
    cudaGetSymbolAddress((void**)&qt,   g_qt);
    cudaGetSymbolAddress((void**)&kt,   g_kt);
    cudaGetSymbolAddress((void**)&vt,   g_vt);
    cudaGetSymbolAddress((void**)&xh,   g_xh);
    cudaGetSymbolAddress((void**)&wqkv, g_wqkv);
    cudaGetSymbolAddress((void**)&wo,   g_wo);
    cudaGetSymbolAddress((void**)&ctx,  g_ctx);

    cudaFuncSetAttribute(flash_fp16_kernel, cudaFuncAttributeMaxDynamicSharedMemorySize,
                         FLASH_SMEM);

    // 0: rope table
    rope_table_kernel<<<TT / 2, 128>>>();
    // 1: x -> fp16
    conv_half_kernel<<<(unsigned)(((size_t)MM * HH / 4 + 255) / 256), 256>>>(
        x, xh, (size_t)MM * HH);
    // 2-4: W^T fp16 (QKV into one buffer)
    wt_half_kernel<<<dim3(2048 / 32, 2048 / 32), 256>>>(Wq, wqkv, 2048, 2048);
    wt_half_kernel<<<dim3(1024 / 32, 2048 / 32), 256>>>(Wk, wqkv + (size_t)2048 * 2048, 2048, 1024);
    wt_half_kernel<<<dim3(1024 / 32, 2048 / 32), 256>>>(Wv, wqkv + (size_t)3072 * 2048, 2048, 1024);
    // 5: fused QKV projection (N=4096)
    gemm_fp16_kernel<<<dim3(4096 / 128, MM / 128), 256>>>(xh, wqkv, qkvraw, MM, 4096, HH);
    // 6-8: RMSNorm/RoPE/transpose -> fp16
    norm_rope_kernel<<<BB * TT * NH, 128>>>(qkvraw, qt, qnw, NH, 4096);
    norm_rope_kernel<<<BB * TT * NKV, 128>>>(qkvraw + 2048, kt, knw, NKV, 4096);
    transpose_kernel<<<BB * TT * NKV, 128>>>(qkvraw + 3072, vt, NKV, 4096);
    // 9: Wo^T fp16
    wt_half_kernel<<<dim3(2048 / 32, 2048 / 32), 256>>>(Wo, wo, 2048, 2048);
    // 10: flash attention (paired Q-tiles, uniform 33 iters/CTA)
    flash_fp16_kernel<<<dim3(NQB / 2, BB * NKV), 256, FLASH_SMEM>>>(qt, kt, vt, ctx);
    // 11: output projection
    gemm_fp16_kernel<<<dim3(2048 / 128, MM / 128), 256>>>(ctx, wo, out, MM, 2048, HH);
}

// round 12
// speedup vs baseline: 1.0665x; 1.0197x over previous
#include <cuda_runtime.h>
#include <cuda_fp16.h>
#include <cstdint>
#include <cstddef>
#include <math.h>

// Problem constants
#define BB   2
#define TT   2048
#define HH   2048
#define NH   16
#define NKV  8
#define HD   128
#define MM   (BB*TT)            // 4096 rows

// ---------------- scratch (static device globals; no allocation) -------------
__device__ float g_qkvraw[(size_t)MM * 4096];      // [b*T+t, {Q|K|V}]
__device__ __half g_qt[(size_t)BB * NH * TT * HD]; // [b,h,t,d] fp16
__device__ __half g_kt[(size_t)BB * NKV * TT * HD];
__device__ __half g_vt[(size_t)BB * NKV * TT * HD];
__device__ __half g_xh[(size_t)MM * HH];           // x fp16
__device__ __half g_wqkv[(size_t)4096 * 2048];     // [N=4096, K=2048] fp16 (Q|K|V rows)
__device__ __half g_wo[(size_t)2048 * 2048];       // Wo^T [N,K] fp16
__device__ __half g_ctx[(size_t)MM * HH];          // [b*T+t, h*HD+d] fp16
__device__ float g_cos[TT * 64];
__device__ float g_sin[TT * 64];

// ---------------- helpers ----------------------------------------------------
__device__ __forceinline__ uint32_t smem_u32(const void* p) {
    uint32_t a;
    asm("{ .reg .u64 t; cvta.to.shared.u64 t, %1; cvt.u32.u64 %0, t; }" : "=r"(a) : "l"(p));
    return a;
}

__device__ __forceinline__ void mma_f16(float c[4], const uint32_t a[4],
                                        uint32_t b0, uint32_t b1) {
    asm volatile(
        "mma.sync.aligned.m16n8k16.row.col.f32.f16.f16.f32 "
        "{%0,%1,%2,%3}, {%4,%5,%6,%7}, {%8,%9}, {%0,%1,%2,%3};\n"
        : "+f"(c[0]), "+f"(c[1]), "+f"(c[2]), "+f"(c[3])
        : "r"(a[0]), "r"(a[1]), "r"(a[2]), "r"(a[3]), "r"(b0), "r"(b1));
}

#define LDSM_X4(R0,R1,R2,R3,ADDR)                                              \
    asm volatile("ldmatrix.sync.aligned.m8n8.x4.shared.b16 {%0,%1,%2,%3}, [%4];" \
        : "=r"(R0), "=r"(R1), "=r"(R2), "=r"(R3) : "r"(ADDR))
#define LDSM_X4T(R0,R1,R2,R3,ADDR)                                             \
    asm volatile("ldmatrix.sync.aligned.m8n8.x4.trans.shared.b16 {%0,%1,%2,%3}, [%4];" \
        : "=r"(R0), "=r"(R1), "=r"(R2), "=r"(R3) : "r"(ADDR))

#define CP_ASYNC16(SMEM, GPTR) \
    asm volatile("cp.async.cg.shared.global [%0], [%1], 16;" :: "r"(SMEM), "l"(GPTR) : "memory")
#define CP_COMMIT() asm volatile("cp.async.commit_group;" ::: "memory")
#define CP_WAIT1()  asm volatile("cp.async.wait_group 1;" ::: "memory")
#define CP_WAIT0()  asm volatile("cp.async.wait_group 0;" ::: "memory")

// ---------------- RoPE tables (fp64 angle, fp32 trig after reduction) ---------
__global__ void rope_table_kernel() {
    int t = blockIdx.x * 2 + (threadIdx.x >> 6);
    int j = threadIdx.x & 63;  // 0..63
    double inv = exp(-(double)j * (13.815510557964274 / 64.0)); // theta=1e6
    double ang = (double)t * inv;
    const double TWO_PI = 6.283185307179586476925286766559;
    double red = ang - TWO_PI * floor(ang * (1.0 / TWO_PI));
    float c, s;
    sincosf((float)red, &s, &c);
    g_cos[t * 64 + j] = c;
    g_sin[t * 64 + j] = s;
}

// ---------------- merged prep: x->fp16 + 4 weight transposes ------------------
// blocks [0, 8192)            : conv x (8,388,608 elems / 4 per thread / 256)
// blocks [8192, 12288)        : Wq  transpose tiles (64 x 64)
// blocks [12288, 14336)       : Wk  (32 x 64)
// blocks [14336, 16384)       : Wv  (32 x 64)
// blocks [16384, 20480)       : Wo  (64 x 64)
#define PREP_BLOCKS 20480
__global__ __launch_bounds__(256) void prep_kernel(
    const float* __restrict__ x,
    const float* __restrict__ Wq, const float* __restrict__ Wk,
    const float* __restrict__ Wv, const float* __restrict__ Wo,
    __half* __restrict__ xh, __half* __restrict__ wqkv, __half* __restrict__ wo)
{
    __shared__ float t[32][33];
    int bid = blockIdx.x;
    int tid = threadIdx.x;

    if (bid < 8192) {
        size_t i = ((size_t)bid * 256 + tid) * 4;
        float4 v = *(const float4*)(x + i);
        *(__half2*)(xh + i)     = __floats2half2_rn(v.x, v.y);
        *(__half2*)(xh + i + 2) = __floats2half2_rn(v.z, v.w);
        return;
    }
    bid -= 8192;

    const float* W; __half* Wt; int N_;
    if (bid < 4096)      { W = Wq; Wt = wqkv;                        N_ = 2048; }
    else if (bid < 6144) { bid -= 4096; W = Wk; Wt = wqkv + (size_t)2048 * 2048; N_ = 1024; }
    else if (bid < 8192) { bid -= 6144; W = Wv; Wt = wqkv + (size_t)3072 * 2048; N_ = 1024; }
    else                 { bid -= 8192; W = Wo; Wt = wo;             N_ = 2048; }

    const int K = 2048;
    int tilesX = N_ / 32;
    int n0 = (bid % tilesX) * 32, k0 = (bid / tilesX) * 32;
    int tx = tid & 31, ty = tid >> 5;   // 32 x 8
    #pragma unroll
    for (int i = 0; i < 32; i += 8)
        t[ty + i][tx] = W[(size_t)(k0 + ty + i) * N_ + n0 + tx];
    __syncthreads();
    #pragma unroll
    for (int i = 0; i < 32; i += 8)
        Wt[(size_t)(n0 + ty + i) * K + k0 + tx] = __float2half(t[tx][ty + i]);
}

// ---------------- fp16 tensor-core GEMM: C[M,N] = A[M,K] @ B[N,K]^T -----------
// BK=32, double-buffered smem, ldmatrix fragment loads.
#define GAS 40   // smem row stride in halves (80B = 5x16B, odd -> ldmatrix clean)
#define GSTG (128 * GAS)
__global__ __launch_bounds__(256, 2) void gemm_fp16_kernel(
    const __half* __restrict__ A, const __half* __restrict__ Bm,
    float* __restrict__ C, int M, int N_, int K)
{
    __shared__ __half As[2 * GSTG];
    __shared__ __half Bs[2 * GSTG];

    int tid = threadIdx.x;
    int wid = tid >> 5, lane = tid & 31;
    int g = lane >> 2, tg = lane & 3;
    int lr = lane & 7;
    int lm = (lane >> 3) & 1;
    int lh = lane >> 4;
    int sel = lane >> 3;
    int warpRow = wid >> 1, warpCol = wid & 1;  // 4 x 2 warps
    int brow = blockIdx.y * 128, bcol = blockIdx.x * 128;

    int rowL[2], segL[2];
    #pragma unroll
    for (int it = 0; it < 2; ++it) {
        int idx = it * 256 + tid;
        rowL[it] = idx >> 2;
        segL[it] = (idx & 3) * 8;
    }
    const __half* ApL[2];
    const __half* BpL[2];
    #pragma unroll
    for (int it = 0; it < 2; ++it) {
        ApL[it] = A  + (size_t)(brow + rowL[it]) * K + segL[it];
        BpL[it] = Bm + (size_t)(bcol + rowL[it]) * K + segL[it];
    }

    uint32_t sA = smem_u32(As), sB = smem_u32(Bs);

    float acc[2][8][4];
    #pragma unroll
    for (int mi = 0; mi < 2; mi++)
        #pragma unroll
        for (int ni = 0; ni < 8; ni++)
            #pragma unroll
            for (int c = 0; c < 4; c++) acc[mi][ni][c] = 0.f;

    #pragma unroll
    for (int it = 0; it < 2; ++it) {
        *(int4*)&As[rowL[it] * GAS + segL[it]] = *(const int4*)ApL[it];
        *(int4*)&Bs[rowL[it] * GAS + segL[it]] = *(const int4*)BpL[it];
    }
    __syncthreads();

    int buf = 0;
    for (int k0 = 0; k0 < K; k0 += 32) {
        int4 pa[2], pb[2];
        bool more = (k0 + 32 < K);
        if (more) {
            #pragma unroll
            for (int it = 0; it < 2; ++it) {
                pa[it] = *(const int4*)(ApL[it] + k0 + 32);
                pb[it] = *(const int4*)(BpL[it] + k0 + 32);
            }
        }

        uint32_t bA = sA + buf * (GSTG * 2);
        uint32_t bB = sB + buf * (GSTG * 2);
        #pragma unroll
        for (int ks = 0; ks < 2; ++ks) {
            int kk = ks * 16;
            uint32_t af[2][4];
            #pragma unroll
            for (int mi = 0; mi < 2; mi++) {
                uint32_t addr = bA + (uint32_t)(((warpRow * 32 + mi * 16 + lr + lm * 8) * GAS
                                                 + kk + lh * 8) * 2);
                LDSM_X4(af[mi][0], af[mi][1], af[mi][2], af[mi][3], addr);
            }
            uint32_t bf[8][2];
            #pragma unroll
            for (int nb = 0; nb < 4; nb++) {
                int n0 = warpCol * 64 + nb * 16;
                uint32_t addr = bB + (uint32_t)(((n0 + lr + (sel >> 1) * 8) * GAS
                                                 + kk + (sel & 1) * 8) * 2);
                LDSM_X4(bf[2 * nb][0], bf[2 * nb][1], bf[2 * nb + 1][0], bf[2 * nb + 1][1], addr);
            }
            #pragma unroll
            for (int mi = 0; mi < 2; mi++)
                #pragma unroll
                for (int ni = 0; ni < 8; ni++)
                    mma_f16(acc[mi][ni], af[mi], bf[ni][0], bf[ni][1]);
        }

        if (more) {
            __half* Ad = As + (buf ^ 1) * GSTG;
            __half* Bd = Bs + (buf ^ 1) * GSTG;
            #pragma unroll
            for (int it = 0; it < 2; ++it) {
                *(int4*)&Ad[rowL[it] * GAS + segL[it]] = pa[it];
                *(int4*)&Bd[rowL[it] * GAS + segL[it]] = pb[it];
            }
        }
        __syncthreads();
        buf ^= 1;
    }

    #pragma unroll
    for (int mi = 0; mi < 2; mi++) {
        int r0 = brow + warpRow * 32 + mi * 16 + g;
        #pragma unroll
        for (int ni = 0; ni < 8; ni++) {
            int cn = bcol + warpCol * 64 + ni * 8 + tg * 2;
            *(float2*)(C + (size_t)r0 * N_ + cn) = make_float2(acc[mi][ni][0], acc[mi][ni][1]);
            *(float2*)(C + (size_t)(r0 + 8) * N_ + cn) = make_float2(acc[mi][ni][2], acc[mi][ni][3]);
        }
    }
}

// ------------- merged RMSNorm+RoPE (Q,K) + V transpose -> fp16 ----------------
// blocks [0, 65536)        : Q heads  (nheads=NH,  src col 0,    dst qt, w=qnw)
// blocks [65536, 98304)    : K heads  (nheads=NKV, src col 2048, dst kt, w=knw)
// blocks [98304, 131072)   : V heads  (transpose only)
#define NORMV_BLOCKS (BB * TT * (NH + 2 * NKV))
__global__ __launch_bounds__(128) void normv_kernel(
    const float* __restrict__ qkvraw,
    __half* __restrict__ qt, __half* __restrict__ kt, __half* __restrict__ vt,
    const float* __restrict__ qnw, const float* __restrict__ knw)
{
    int r = blockIdx.x;
    int d = threadIdx.x;             // 0..127

    const float* src; __half* dst; const float* w; int nheads; bool donorm;
    if (r < BB * TT * NH) {
        src = qkvraw;            dst = qt; w = qnw; nheads = NH;  donorm = true;
    } else if (r < BB * TT * (NH + NKV)) {
        r -= BB * TT * NH;
        src = qkvraw + 2048;     dst = kt; w = knw; nheads = NKV; donorm = true;
    } else {
        r -= BB * TT * (NH + NKV);
        src = qkvraw + 3072;     dst = vt; w = qnw; nheads = NKV; donorm = false;
    }

    int h  = r % nheads;
    int bt = r / nheads;
    int t  = bt % TT;
    int b  = bt / TT;

    float val = src[(size_t)bt * 4096 + h * HD + d];

    if (!donorm) {
        vt[((size_t)(b * nheads + h) * TT + t) * HD + d] = __float2half(val);
        return;
    }

    __shared__ float red[4];
    __shared__ float sh[HD];

    float ss = val * val;
    #pragma unroll
    for (int off = 16; off; off >>= 1)
        ss += __shfl_xor_sync(0xffffffffu, ss, off);
    if ((d & 31) == 0) red[d >> 5] = ss;
    __syncthreads();
    float tot = red[0] + red[1] + red[2] + red[3];
    float nv = val * rsqrtf(tot * (1.0f / HD) + 1e-6f) * w[d];
    sh[d] = nv;
    __syncthreads();

    int j = d & 63;
    float c = g_cos[t * 64 + j];
    float s = g_sin[t * 64 + j];
    float other = (d < 64) ? -sh[d + 64] : sh[d - 64];
    float out = nv * c + other * s;

    dst[((size_t)(b * nheads + h) * TT + t) * HD + d] = __float2half(out);
}

// ------------- Causal flash attention: fp16 mma, cp.async pipeline ------------
// Paired Q-tiles per CTA: phase 0 -> qb = x, phase 1 -> qb = 31-x; every CTA
// does exactly 33 tile-iterations (perfect balance). 2 GQA heads per CTA.
#define US_STR 136   // halves; 272B rows -> ldmatrix conflict-free
#define PS_STR 72
#define FL_KV  (64 * US_STR)
#define FL_U   (128 * US_STR)
#define FLASH_SMEM ((2 * FL_KV + FL_U) * 2)
#define NQB    (TT / 64)         // 32 q-blocks

__global__ __launch_bounds__(256) void flash_fp16_kernel(
    const __half* __restrict__ Q, const __half* __restrict__ Kt,
    const __half* __restrict__ Vt, __half* __restrict__ ctx)
{
    extern __shared__ __half smh[];
    __half* Ks = smh;
    __half* Vs = smh + FL_KV;
    __half* Us = smh + 2 * FL_KV;
    __half* Ps = Us;

    int tid = threadIdx.x;
    int wid = tid >> 5, lane = tid & 31;
    int g = lane >> 2, tg = lane & 3;
    int lr = lane & 7;
    int lm = (lane >> 3) & 1;
    int lh = lane >> 4;
    int p8 = (lane >> 3) & 1;
    int p16 = lane >> 4;

    int hw = wid >> 2;
    int w4 = wid & 3;
    int base = w4 * 16;

    int qbx = blockIdx.x;            // 0..15
    int bk = blockIdx.y;
    int b = bk / NKV, kvh = bk % NKV;
    int h = kvh * 2 + hw;

    const __half* Kbase = Kt + ((size_t)(b * NKV + kvh) * TT) * HD;
    const __half* Vbase = Vt + ((size_t)(b * NKV + kvh) * TT) * HD;

    uint32_t sK = smem_u32(Ks), sV = smem_u32(Vs), sU = smem_u32(Us), sP = sU;

    int cprow[4], cpc8[4];
    uint32_t cpK[4], cpV[4];
    #pragma unroll
    for (int it = 0; it < 4; ++it) {
        int idx = it * 256 + tid;
        cprow[it] = idx >> 4;
        cpc8[it]  = (idx & 15) * 8;
        cpK[it] = sK + (uint32_t)((cprow[it] * US_STR + cpc8[it]) * 2);
        cpV[it] = sV + (uint32_t)((cprow[it] * US_STR + cpc8[it]) * 2);
    }

    const float scale = 0.08838834764831845f;   // 128^-0.5
    const float L2E = 1.44269504088896f;

    for (int ph = 0; ph < 2; ++ph) {
        int qb = ph ? (NQB - 1 - qbx) : qbx;

        CP_WAIT0();
        __syncthreads();

        #pragma unroll
        for (int it = 0; it < 4; ++it)
            CP_ASYNC16(cpK[it], Kbase + (size_t)cprow[it] * HD + cpc8[it]);
        CP_COMMIT();
        #pragma unroll
        for (int it = 0; it < 4; ++it)
            CP_ASYNC16(cpV[it], Vbase + (size_t)cprow[it] * HD + cpc8[it]);
        CP_COMMIT();

        {
            const __half* Qh = Q + ((size_t)(b * NH + kvh * 2 + hw) * TT + qb * 64) * HD;
            int t128 = tid & 127;
            #pragma unroll
            for (int it = 0; it < 8; ++it) {
                int idx = it * 128 + t128;
                int r = idx >> 4;
                int c8 = (idx & 15) * 8;
                *(int4*)&Us[(hw * 64 + r) * US_STR + c8] =
                    *(const int4*)(Qh + (size_t)r * HD + c8);
            }
        }
        __syncthreads();

        uint32_t qa[8][4];
        #pragma unroll
        for (int ks = 0; ks < 8; ++ks) {
            uint32_t au = sU + (uint32_t)(((hw * 64 + base + lr + lm * 8) * US_STR + ks * 16 + lh * 8) * 2);
            LDSM_X4(qa[ks][0], qa[ks][1], qa[ks][2], qa[ks][3], au);
        }

        float o[16][4];
        #pragma unroll
        for (int ni = 0; ni < 16; ni++)
            #pragma unroll
            for (int c = 0; c < 4; c++) o[ni][c] = 0.f;
        float mrow[2] = {-1e30f, -1e30f};
        float lrow[2] = {0.f, 0.f};

        for (int kb = 0; kb <= qb; ++kb) {
            bool more = (kb < qb);
            CP_WAIT1();
            __syncthreads();

            float s[8][4];
            #pragma unroll
            for (int ni = 0; ni < 8; ni++)
                #pragma unroll
                for (int c = 0; c < 4; c++) s[ni][c] = 0.f;

            #pragma unroll
            for (int ks = 0; ks < 8; ++ks) {
                int kk = ks * 16;
                #pragma unroll
                for (int np = 0; np < 4; np++) {
                    uint32_t r0, r1, r2, r3;
                    uint32_t ak = sK + (uint32_t)(((np * 16 + p16 * 8 + lr) * US_STR
                                                   + kk + p8 * 8) * 2);
                    LDSM_X4(r0, r1, r2, r3, ak);
                    mma_f16(s[2 * np],     qa[ks], r0, r1);
                    mma_f16(s[2 * np + 1], qa[ks], r2, r3);
                }
            }
            __syncthreads();

            if (more) {
                const __half* Kn = Kbase + (size_t)(kb + 1) * 64 * HD;
                #pragma unroll
                for (int it = 0; it < 4; ++it)
                    CP_ASYNC16(cpK[it], Kn + (size_t)cprow[it] * HD + cpc8[it]);
            }
            CP_COMMIT();

            bool diag = (kb == qb);
            int rowA = base + g;
            int rowB = rowA + 8;
            float mA = -1e30f, mB = -1e30f;
            #pragma unroll
            for (int ni = 0; ni < 8; ni++) {
                #pragma unroll
                for (int c = 0; c < 4; c++) {
                    float sv = s[ni][c] * scale;
                    if (diag) {
                        int kcol = ni * 8 + tg * 2 + (c & 1);
                        int qrow = (c < 2) ? rowA : rowB;
                        if (kcol > qrow) sv = -1e30f;
                    }
                    s[ni][c] = sv;
                }
                mA = fmaxf(mA, fmaxf(s[ni][0], s[ni][1]));
                mB = fmaxf(mB, fmaxf(s[ni][2], s[ni][3]));
            }
            #pragma unroll
            for (int off = 1; off < 4; off <<= 1) {
                mA = fmaxf(mA, __shfl_xor_sync(0xffffffffu, mA, off));
                mB = fmaxf(mB, __shfl_xor_sync(0xffffffffu, mB, off));
            }
            float mnA = fmaxf(mrow[0], mA);
            float mnB = fmaxf(mrow[1], mB);
            float alA = exp2f((mrow[0] - mnA) * L2E);
            float alB = exp2f((mrow[1] - mnB) * L2E);
            mrow[0] = mnA; mrow[1] = mnB;

            float lA = 0.f, lB = 0.f;
            #pragma unroll
            for (int ni = 0; ni < 8; ni++) {
                s[ni][0] = exp2f((s[ni][0] - mnA) * L2E);
                s[ni][1] = exp2f((s[ni][1] - mnA) * L2E);
                s[ni][2] = exp2f((s[ni][2] - mnB) * L2E);
                s[ni][3] = exp2f((s[ni][3] - mnB) * L2E);
                lA += s[ni][0] + s[ni][1];
                lB += s[ni][2] + s[ni][3];
            }
            #pragma unroll
            for (int off = 1; off < 4; off <<= 1) {
                lA += __shfl_xor_sync(0xffffffffu, lA, off);
                lB += __shfl_xor_sync(0xffffffffu, lB, off);
            }
            lrow[0] = lrow[0] * alA + lA;
            lrow[1] = lrow[1] * alB + lB;
            #pragma unroll
            for (int ni = 0; ni < 16; ni++) {
                o[ni][0] *= alA; o[ni][1] *= alA;
                o[ni][2] *= alB; o[ni][3] *= alB;
            }

            int prowA = hw * 64 + rowA;
            int prowB = hw * 64 + rowB;
            #pragma unroll
            for (int ni = 0; ni < 8; ni++) {
                int cn = ni * 8 + tg * 2;
                *(__half2*)&Ps[prowA * PS_STR + cn] = __floats2half2_rn(s[ni][0], s[ni][1]);
                *(__half2*)&Ps[prowB * PS_STR + cn] = __floats2half2_rn(s[ni][2], s[ni][3]);
            }
            __syncwarp();

            CP_WAIT1();
            __syncthreads();

            #pragma unroll
            for (int ks = 0; ks < 4; ++ks) {
                int kk = ks * 16;
                uint32_t pa4[4];
                uint32_t ap = sP + (uint32_t)(((hw * 64 + base + lr + lm * 8) * PS_STR + kk + lh * 8) * 2);
                LDSM_X4(pa4[0], pa4[1], pa4[2], pa4[3], ap);
                #pragma unroll
                for (int np = 0; np < 8; np++) {
                    uint32_t r0, r1, r2, r3;
                    uint32_t av = sV + (uint32_t)(((kk + p8 * 8 + lr) * US_STR
                                                   + np * 16 + p16 * 8) * 2);
                    LDSM_X4T(r0, r1, r2, r3, av);
                    mma_f16(o[2 * np],     pa4, r0, r1);
                    mma_f16(o[2 * np + 1], pa4, r2, r3);
                }
            }
            __syncthreads();

            if (more) {
                const __half* Vn = Vbase + (size_t)(kb + 1) * 64 * HD;
                #pragma unroll
                for (int it = 0; it < 4; ++it)
                    CP_ASYNC16(cpV[it], Vn + (size_t)cprow[it] * HD + cpc8[it]);
            }
            CP_COMMIT();
        }

        float ivA = 1.0f / lrow[0];
        float ivB = 1.0f / lrow[1];
        int qA = qb * 64 + base + g;
        int qB = qA + 8;
        size_t offA = (size_t)(b * TT + qA) * (NH * HD) + h * HD;
        size_t offB = (size_t)(b * TT + qB) * (NH * HD) + h * HD;
        #pragma unroll
        for (int ni = 0; ni < 16; ni++) {
            int dn = ni * 8 + tg * 2;
            *(__half2*)(ctx + offA + dn) = __floats2half2_rn(o[ni][0] * ivA, o[ni][1] * ivA);
            *(__half2*)(ctx + offB + dn) = __floats2half2_rn(o[ni][2] * ivB, o[ni][3] * ivB);
        }
    }
}

// ---------------------------- launch -----------------------------------------
extern "C" void kernel_launch(void* const* d_in, const int* in_sizes, int n_in,
                              void* d_out, int out_size)
{
    const float* x    = (const float*)d_in[0];
    // d_in[1] = attn_mask (pure causal; applied analytically)
    const float* Wq   = (const float*)d_in[2];
    const float* Wk   = (const float*)d_in[3];
    const float* Wv   = (const float*)d_in[4];
    const float* Wo   = (const float*)d_in[5];
    const float* qnw  = (const float*)d_in[6];
    const float* knw  = (const float*)d_in[7];
    float* out = (float*)d_out;

    float *qkvraw;
    __half *qt, *kt, *vt, *xh, *wqkv, *wo, *ctx;
    cudaGetSymbolAddress((void**)&qkvraw, g_qkvraw);
    cudaGetSymbolAddress((void**)&qt,   g_qt);
    cudaGetSymbolAddress((void**)&kt,   g_kt);
    cudaGetSymbolAddress((void**)&vt,   g_vt);
    cudaGetSymbolAddress((void**)&xh,   g_xh);
    cudaGetSymbolAddress((void**)&wqkv, g_wqkv);
    cudaGetSymbolAddress((void**)&wo,   g_wo);
    cudaGetSymbolAddress((void**)&ctx,  g_ctx);

    cudaFuncSetAttribute(flash_fp16_kernel, cudaFuncAttributeMaxDynamicSharedMemorySize,
                         FLASH_SMEM);

    // 0: rope table
    rope_table_kernel<<<TT / 2, 128>>>();
    // 1: merged prep (x->fp16, Wq/Wk/Wv/Wo transposed fp16)
    prep_kernel<<<PREP_BLOCKS, 256>>>(x, Wq, Wk, Wv, Wo, xh, wqkv, wo);
    // 2: fused QKV projection (N=4096)
    gemm_fp16_kernel<<<dim3(4096 / 128, MM / 128), 256>>>(xh, wqkv, qkvraw, MM, 4096, HH);
    // 3: merged RMSNorm/RoPE (Q,K) + V transpose
    normv_kernel<<<NORMV_BLOCKS, 128>>>(qkvraw, qt, kt, vt, qnw, knw);
    // 4: flash attention (paired Q-tiles, uniform 33 iters/CTA)
    flash_fp16_kernel<<<dim3(NQB / 2, BB * NKV), 256, FLASH_SMEM>>>(qt, kt, vt, ctx);
    // 5: output projection
    gemm_fp16_kernel<<<dim3(2048 / 128, MM / 128), 256>>>(ctx, wo, out, MM, 2048, HH);
}

// round 13
// speedup vs baseline: 1.1486x; 1.0770x over previous
#include <cuda_runtime.h>
#include <cuda_fp16.h>
#include <cstdint>
#include <cstddef>
#include <math.h>

// Problem constants
#define BB   2
#define TT   2048
#define HH   2048
#define NH   16
#define NKV  8
#define HD   128
#define MM   (BB*TT)            // 4096 rows

// ---------------- scratch (static device globals; no allocation) -------------
__device__ float g_qkvraw[(size_t)MM * 4096];      // [b*T+t, {Q|K|V}]
__device__ __half g_qt[(size_t)BB * NH * TT * HD]; // [b,h,t,d] fp16
__device__ __half g_kt[(size_t)BB * NKV * TT * HD];
__device__ __half g_vt[(size_t)BB * NKV * TT * HD];
__device__ __half g_xh[(size_t)MM * HH];           // x fp16
__device__ __half g_wqkv[(size_t)4096 * 2048];     // [N=4096, K=2048] fp16 (Q|K|V rows)
__device__ __half g_wo[(size_t)2048 * 2048];       // Wo^T [N,K] fp16
__device__ __half g_ctx[(size_t)MM * HH];          // [b*T+t, h*HD+d] fp16
__device__ float g_cos[TT * 64];
__device__ float g_sin[TT * 64];

// ---------------- helpers ----------------------------------------------------
__device__ __forceinline__ uint32_t smem_u32(const void* p) {
    uint32_t a;
    asm("{ .reg .u64 t; cvta.to.shared.u64 t, %1; cvt.u32.u64 %0, t; }" : "=r"(a) : "l"(p));
    return a;
}

__device__ __forceinline__ void mma_f16(float c[4], const uint32_t a[4],
                                        uint32_t b0, uint32_t b1) {
    asm volatile(
        "mma.sync.aligned.m16n8k16.row.col.f32.f16.f16.f32 "
        "{%0,%1,%2,%3}, {%4,%5,%6,%7}, {%8,%9}, {%0,%1,%2,%3};\n"
        : "+f"(c[0]), "+f"(c[1]), "+f"(c[2]), "+f"(c[3])
        : "r"(a[0]), "r"(a[1]), "r"(a[2]), "r"(a[3]), "r"(b0), "r"(b1));
}

#define LDSM_X4(R0,R1,R2,R3,ADDR)                                              \
    asm volatile("ldmatrix.sync.aligned.m8n8.x4.shared.b16 {%0,%1,%2,%3}, [%4];" \
        : "=r"(R0), "=r"(R1), "=r"(R2), "=r"(R3) : "r"(ADDR))
#define LDSM_X4T(R0,R1,R2,R3,ADDR)                                             \
    asm volatile("ldmatrix.sync.aligned.m8n8.x4.trans.shared.b16 {%0,%1,%2,%3}, [%4];" \
        : "=r"(R0), "=r"(R1), "=r"(R2), "=r"(R3) : "r"(ADDR))

#define CP_ASYNC16(SMEM, GPTR) \
    asm volatile("cp.async.cg.shared.global [%0], [%1], 16;" :: "r"(SMEM), "l"(GPTR) : "memory")
#define CP_COMMIT() asm volatile("cp.async.commit_group;" ::: "memory")
#define CP_WAIT1()  asm volatile("cp.async.wait_group 1;" ::: "memory")
#define CP_WAIT0()  asm volatile("cp.async.wait_group 0;" ::: "memory")

// ---------------- RoPE tables (fp64 angle, fp32 trig after reduction) ---------
__global__ void rope_table_kernel() {
    int t = blockIdx.x * 2 + (threadIdx.x >> 6);
    int j = threadIdx.x & 63;  // 0..63
    double inv = exp(-(double)j * (13.815510557964274 / 64.0)); // theta=1e6
    double ang = (double)t * inv;
    const double TWO_PI = 6.283185307179586476925286766559;
    double red = ang - TWO_PI * floor(ang * (1.0 / TWO_PI));
    float c, s;
    sincosf((float)red, &s, &c);
    g_cos[t * 64 + j] = c;
    g_sin[t * 64 + j] = s;
}

// ---------------- merged prep: x->fp16 + 4 weight transposes ------------------
#define PREP_BLOCKS 20480
__global__ __launch_bounds__(256) void prep_kernel(
    const float* __restrict__ x,
    const float* __restrict__ Wq, const float* __restrict__ Wk,
    const float* __restrict__ Wv, const float* __restrict__ Wo,
    __half* __restrict__ xh, __half* __restrict__ wqkv, __half* __restrict__ wo)
{
    __shared__ float t[32][33];
    int bid = blockIdx.x;
    int tid = threadIdx.x;

    if (bid < 8192) {
        size_t i = ((size_t)bid * 256 + tid) * 4;
        float4 v = *(const float4*)(x + i);
        *(__half2*)(xh + i)     = __floats2half2_rn(v.x, v.y);
        *(__half2*)(xh + i + 2) = __floats2half2_rn(v.z, v.w);
        return;
    }
    bid -= 8192;

    const float* W; __half* Wt; int N_;
    if (bid < 4096)      { W = Wq; Wt = wqkv;                        N_ = 2048; }
    else if (bid < 6144) { bid -= 4096; W = Wk; Wt = wqkv + (size_t)2048 * 2048; N_ = 1024; }
    else if (bid < 8192) { bid -= 6144; W = Wv; Wt = wqkv + (size_t)3072 * 2048; N_ = 1024; }
    else                 { bid -= 8192; W = Wo; Wt = wo;             N_ = 2048; }

    const int K = 2048;
    int tilesX = N_ / 32;
    int n0 = (bid % tilesX) * 32, k0 = (bid / tilesX) * 32;
    int tx = tid & 31, ty = tid >> 5;   // 32 x 8
    #pragma unroll
    for (int i = 0; i < 32; i += 8)
        t[ty + i][tx] = W[(size_t)(k0 + ty + i) * N_ + n0 + tx];
    __syncthreads();
    #pragma unroll
    for (int i = 0; i < 32; i += 8)
        Wt[(size_t)(n0 + ty + i) * K + k0 + tx] = __float2half(t[tx][ty + i]);
}

// ---------------- fp16 tensor-core GEMM: C[M,N] = A[M,K] @ B[N,K]^T -----------
// BK=32, double-buffered smem, ldmatrix fragment loads.
#define GAS 40   // smem row stride in halves (80B = 5x16B, odd -> ldmatrix clean)
#define GSTG (128 * GAS)
__global__ __launch_bounds__(256, 2) void gemm_fp16_kernel(
    const __half* __restrict__ A, const __half* __restrict__ Bm,
    float* __restrict__ C, int M, int N_, int K)
{
    __shared__ __half As[2 * GSTG];
    __shared__ __half Bs[2 * GSTG];

    int tid = threadIdx.x;
    int wid = tid >> 5, lane = tid & 31;
    int g = lane >> 2, tg = lane & 3;
    int lr = lane & 7;
    int lm = (lane >> 3) & 1;
    int lh = lane >> 4;
    int sel = lane >> 3;
    int warpRow = wid >> 1, warpCol = wid & 1;  // 4 x 2 warps
    int brow = blockIdx.y * 128, bcol = blockIdx.x * 128;

    int rowL[2], segL[2];
    #pragma unroll
    for (int it = 0; it < 2; ++it) {
        int idx = it * 256 + tid;
        rowL[it] = idx >> 2;
        segL[it] = (idx & 3) * 8;
    }
    const __half* ApL[2];
    const __half* BpL[2];
    #pragma unroll
    for (int it = 0; it < 2; ++it) {
        ApL[it] = A  + (size_t)(brow + rowL[it]) * K + segL[it];
        BpL[it] = Bm + (size_t)(bcol + rowL[it]) * K + segL[it];
    }

    uint32_t sA = smem_u32(As), sB = smem_u32(Bs);

    float acc[2][8][4];
    #pragma unroll
    for (int mi = 0; mi < 2; mi++)
        #pragma unroll
        for (int ni = 0; ni < 8; ni++)
            #pragma unroll
            for (int c = 0; c < 4; c++) acc[mi][ni][c] = 0.f;

    #pragma unroll
    for (int it = 0; it < 2; ++it) {
        *(int4*)&As[rowL[it] * GAS + segL[it]] = *(const int4*)ApL[it];
        *(int4*)&Bs[rowL[it] * GAS + segL[it]] = *(const int4*)BpL[it];
    }
    __syncthreads();

    int buf = 0;
    for (int k0 = 0; k0 < K; k0 += 32) {
        int4 pa[2], pb[2];
        bool more = (k0 + 32 < K);
        if (more) {
            #pragma unroll
            for (int it = 0; it < 2; ++it) {
                pa[it] = *(const int4*)(ApL[it] + k0 + 32);
                pb[it] = *(const int4*)(BpL[it] + k0 + 32);
            }
        }

        uint32_t bA = sA + buf * (GSTG * 2);
        uint32_t bB = sB + buf * (GSTG * 2);
        #pragma unroll
        for (int ks = 0; ks < 2; ++ks) {
            int kk = ks * 16;
            uint32_t af[2][4];
            #pragma unroll
            for (int mi = 0; mi < 2; mi++) {
                uint32_t addr = bA + (uint32_t)(((warpRow * 32 + mi * 16 + lr + lm * 8) * GAS
                                                 + kk + lh * 8) * 2);
                LDSM_X4(af[mi][0], af[mi][1], af[mi][2], af[mi][3], addr);
            }
            uint32_t bf[8][2];
            #pragma unroll
            for (int nb = 0; nb < 4; nb++) {
                int n0 = warpCol * 64 + nb * 16;
                uint32_t addr = bB + (uint32_t)(((n0 + lr + (sel >> 1) * 8) * GAS
                                                 + kk + (sel & 1) * 8) * 2);
                LDSM_X4(bf[2 * nb][0], bf[2 * nb][1], bf[2 * nb + 1][0], bf[2 * nb + 1][1], addr);
            }
            #pragma unroll
            for (int mi = 0; mi < 2; mi++)
                #pragma unroll
                for (int ni = 0; ni < 8; ni++)
                    mma_f16(acc[mi][ni], af[mi], bf[ni][0], bf[ni][1]);
        }

        if (more) {
            __half* Ad = As + (buf ^ 1) * GSTG;
            __half* Bd = Bs + (buf ^ 1) * GSTG;
            #pragma unroll
            for (int it = 0; it < 2; ++it) {
                *(int4*)&Ad[rowL[it] * GAS + segL[it]] = pa[it];
                *(int4*)&Bd[rowL[it] * GAS + segL[it]] = pb[it];
            }
        }
        __syncthreads();
        buf ^= 1;
    }

    #pragma unroll
    for (int mi = 0; mi < 2; mi++) {
        int r0 = brow + warpRow * 32 + mi * 16 + g;
        #pragma unroll
        for (int ni = 0; ni < 8; ni++) {
            int cn = bcol + warpCol * 64 + ni * 8 + tg * 2;
            *(float2*)(C + (size_t)r0 * N_ + cn) = make_float2(acc[mi][ni][0], acc[mi][ni][1]);
            *(float2*)(C + (size_t)(r0 + 8) * N_ + cn) = make_float2(acc[mi][ni][2], acc[mi][ni][3]);
        }
    }
}

// ------------- merged RMSNorm+RoPE (Q,K) + V convert, warp-per-row ------------
// rows: [0, B*T*NH) Q | [.., +B*T*NKV) K | [.., +B*T*NKV) V
// One warp per 128-elem row: lane holds elems 4l..4l+3; RoPE partner (d^64)
// lives in lane l^16 -> shfl. No smem, no __syncthreads.
#define NORMV_ROWS (BB * TT * (NH + 2 * NKV))    // 131072
__global__ __launch_bounds__(256) void normv_kernel(
    const float* __restrict__ qkvraw,
    __half* __restrict__ qt, __half* __restrict__ kt, __half* __restrict__ vt,
    const float* __restrict__ qnw, const float* __restrict__ knw)
{
    int r = blockIdx.x * 8 + (threadIdx.x >> 5);
    int lane = threadIdx.x & 31;

    const float* src; __half* dst; const float* w; int nheads; bool donorm;
    if (r < BB * TT * NH) {
        src = qkvraw;            dst = qt; w = qnw; nheads = NH;  donorm = true;
    } else if (r < BB * TT * (NH + NKV)) {
        r -= BB * TT * NH;
        src = qkvraw + 2048;     dst = kt; w = knw; nheads = NKV; donorm = true;
    } else {
        r -= BB * TT * (NH + NKV);
        src = qkvraw + 3072;     dst = vt; w = qnw; nheads = NKV; donorm = false;
    }

    int h  = r % nheads;
    int bt = r / nheads;
    int t  = bt % TT;
    int b  = bt / TT;

    int d0 = lane * 4;
    float4 v = *(const float4*)(src + (size_t)bt * 4096 + h * HD + d0);
    __half* outp = dst + ((size_t)(b * nheads + h) * TT + t) * HD + d0;

    if (!donorm) {
        union { __half2 h2[2]; uint2 u; } pk;
        pk.h2[0] = __floats2half2_rn(v.x, v.y);
        pk.h2[1] = __floats2half2_rn(v.z, v.w);
        *(uint2*)outp = pk.u;
        return;
    }

    float ssq = v.x * v.x + v.y * v.y + v.z * v.z + v.w * v.w;
    #pragma unroll
    for (int off = 16; off; off >>= 1)
        ssq += __shfl_xor_sync(0xffffffffu, ssq, off);
    float rinv = rsqrtf(ssq * (1.0f / HD) + 1e-6f);

    float4 wv = *(const float4*)(w + d0);
    float n0 = v.x * rinv * wv.x;
    float n1 = v.y * rinv * wv.y;
    float n2 = v.z * rinv * wv.z;
    float n3 = v.w * rinv * wv.w;

    // partner values at d0 ^ 64 (lane ^ 16)
    float p0 = __shfl_xor_sync(0xffffffffu, n0, 16);
    float p1 = __shfl_xor_sync(0xffffffffu, n1, 16);
    float p2 = __shfl_xor_sync(0xffffffffu, n2, 16);
    float p3 = __shfl_xor_sync(0xffffffffu, n3, 16);

    float sgn = (lane >= 16) ? 1.f : -1.f;
    int j0 = (lane & 15) * 4;
    float4 cc = *(const float4*)(g_cos + t * 64 + j0);
    float4 sc = *(const float4*)(g_sin + t * 64 + j0);

    float o0 = n0 * cc.x + sgn * p0 * sc.x;
    float o1 = n1 * cc.y + sgn * p1 * sc.y;
    float o2 = n2 * cc.z + sgn * p2 * sc.z;
    float o3 = n3 * cc.w + sgn * p3 * sc.w;

    union { __half2 h2[2]; uint2 u; } pk;
    pk.h2[0] = __floats2half2_rn(o0, o1);
    pk.h2[1] = __floats2half2_rn(o2, o3);
    *(uint2*)outp = pk.u;
}

// ------------- Causal flash attention: fp16 mma, cp.async pipeline ------------
// Paired Q-tiles per CTA: phase 0 -> qb = x, phase 1 -> qb = 31-x; every CTA
// does exactly 33 tile-iterations (perfect balance). 2 GQA heads per CTA.
#define US_STR 136   // halves; 272B rows -> ldmatrix conflict-free
#define PS_STR 72
#define FL_KV  (64 * US_STR)
#define FL_U   (128 * US_STR)
#define FLASH_SMEM ((2 * FL_KV + FL_U) * 2)
#define NQB    (TT / 64)         // 32 q-blocks

__global__ __launch_bounds__(256) void flash_fp16_kernel(
    const __half* __restrict__ Q, const __half* __restrict__ Kt,
    const __half* __restrict__ Vt, __half* __restrict__ ctx)
{
    extern __shared__ __half smh[];
    __half* Ks = smh;
    __half* Vs = smh + FL_KV;
    __half* Us = smh + 2 * FL_KV;
    __half* Ps = Us;

    int tid = threadIdx.x;
    int wid = tid >> 5, lane = tid & 31;
    int g = lane >> 2, tg = lane & 3;
    int lr = lane & 7;
    int lm = (lane >> 3) & 1;
    int lh = lane >> 4;
    int p8 = (lane >> 3) & 1;
    int p16 = lane >> 4;

    int hw = wid >> 2;
    int w4 = wid & 3;
    int base = w4 * 16;

    int qbx = blockIdx.x;            // 0..15
    int bk = blockIdx.y;
    int b = bk / NKV, kvh = bk % NKV;
    int h = kvh * 2 + hw;

    const __half* Kbase = Kt + ((size_t)(b * NKV + kvh) * TT) * HD;
    const __half* Vbase = Vt + ((size_t)(b * NKV + kvh) * TT) * HD;

    uint32_t sK = smem_u32(Ks), sV = smem_u32(Vs), sU = smem_u32(Us), sP = sU;

    int cprow[4], cpc8[4];
    uint32_t cpK[4], cpV[4];
    #pragma unroll
    for (int it = 0; it < 4; ++it) {
        int idx = it * 256 + tid;
        cprow[it] = idx >> 4;
        cpc8[it]  = (idx & 15) * 8;
        cpK[it] = sK + (uint32_t)((cprow[it] * US_STR + cpc8[it]) * 2);
        cpV[it] = sV + (uint32_t)((cprow[it] * US_STR + cpc8[it]) * 2);
    }

    const float scale = 0.08838834764831845f;   // 128^-0.5
    const float L2E = 1.44269504088896f;

    for (int ph = 0; ph < 2; ++ph) {
        int qb = ph ? (NQB - 1 - qbx) : qbx;

        CP_WAIT0();
        __syncthreads();

        #pragma unroll
        for (int it = 0; it < 4; ++it)
            CP_ASYNC16(cpK[it], Kbase + (size_t)cprow[it] * HD + cpc8[it]);
        CP_COMMIT();
        #pragma unroll
        for (int it = 0; it < 4; ++it)
            CP_ASYNC16(cpV[it], Vbase + (size_t)cprow[it] * HD + cpc8[it]);
        CP_COMMIT();

        {
            const __half* Qh = Q + ((size_t)(b * NH + kvh * 2 + hw) * TT + qb * 64) * HD;
            int t128 = tid & 127;
            #pragma unroll
            for (int it = 0; it < 8; ++it) {
                int idx = it * 128 + t128;
                int r = idx >> 4;
                int c8 = (idx & 15) * 8;
                *(int4*)&Us[(hw * 64 + r) * US_STR + c8] =
                    *(const int4*)(Qh + (size_t)r * HD + c8);
            }
        }
        __syncthreads();

        uint32_t qa[8][4];
        #pragma unroll
        for (int ks = 0; ks < 8; ++ks) {
            uint32_t au = sU + (uint32_t)(((hw * 64 + base + lr + lm * 8) * US_STR + ks * 16 + lh * 8) * 2);
            LDSM_X4(qa[ks][0], qa[ks][1], qa[ks][2], qa[ks][3], au);
        }

        float o[16][4];
        #pragma unroll
        for (int ni = 0; ni < 16; ni++)
            #pragma unroll
            for (int c = 0; c < 4; c++) o[ni][c] = 0.f;
        float mrow[2] = {-1e30f, -1e30f};
        float lrow[2] = {0.f, 0.f};

        for (int kb = 0; kb <= qb; ++kb) {
            bool more = (kb < qb);
            CP_WAIT1();
            __syncthreads();

            float s[8][4];
            #pragma unroll
            for (int ni = 0; ni < 8; ni++)
                #pragma unroll
                for (int c = 0; c < 4; c++) s[ni][c] = 0.f;

            #pragma unroll
            for (int ks = 0; ks < 8; ++ks) {
                int kk = ks * 16;
                #pragma unroll
                for (int np = 0; np < 4; np++) {
                    uint32_t r0, r1, r2, r3;
                    uint32_t ak = sK + (uint32_t)(((np * 16 + p16 * 8 + lr) * US_STR
                                                   + kk + p8 * 8) * 2);
                    LDSM_X4(r0, r1, r2, r3, ak);
                    mma_f16(s[2 * np],     qa[ks], r0, r1);
                    mma_f16(s[2 * np + 1], qa[ks], r2, r3);
                }
            }
            __syncthreads();

            if (more) {
                const __half* Kn = Kbase + (size_t)(kb + 1) * 64 * HD;
                #pragma unroll
                for (int it = 0; it < 4; ++it)
                    CP_ASYNC16(cpK[it], Kn + (size_t)cprow[it] * HD + cpc8[it]);
            }
            CP_COMMIT();

            bool diag = (kb == qb);
            int rowA = base + g;
            int rowB = rowA + 8;
            float mA = -1e30f, mB = -1e30f;
            #pragma unroll
            for (int ni = 0; ni < 8; ni++) {
                #pragma unroll
                for (int c = 0; c < 4; c++) {
                    float sv = s[ni][c] * scale;
                    if (diag) {
                        int kcol = ni * 8 + tg * 2 + (c & 1);
                        int qrow = (c < 2) ? rowA : rowB;
                        if (kcol > qrow) sv = -1e30f;
                    }
                    s[ni][c] = sv;
                }
                mA = fmaxf(mA, fmaxf(s[ni][0], s[ni][1]));
                mB = fmaxf(mB, fmaxf(s[ni][2], s[ni][3]));
            }
            #pragma unroll
            for (int off = 1; off < 4; off <<= 1) {
                mA = fmaxf(mA, __shfl_xor_sync(0xffffffffu, mA, off));
                mB = fmaxf(mB, __shfl_xor_sync(0xffffffffu, mB, off));
            }
            float mnA = fmaxf(mrow[0], mA);
            float mnB = fmaxf(mrow[1], mB);
            float alA = exp2f((mrow[0] - mnA) * L2E);
            float alB = exp2f((mrow[1] - mnB) * L2E);
            mrow[0] = mnA; mrow[1] = mnB;

            float lA = 0.f, lB = 0.f;
            #pragma unroll
            for (int ni = 0; ni < 8; ni++) {
                s[ni][0] = exp2f((s[ni][0] - mnA) * L2E);
                s[ni][1] = exp2f((s[ni][1] - mnA) * L2E);
                s[ni][2] = exp2f((s[ni][2] - mnB) * L2E);
                s[ni][3] = exp2f((s[ni][3] - mnB) * L2E);
                lA += s[ni][0] + s[ni][1];
                lB += s[ni][2] + s[ni][3];
            }
            #pragma unroll
            for (int off = 1; off < 4; off <<= 1) {
                lA += __shfl_xor_sync(0xffffffffu, lA, off);
                lB += __shfl_xor_sync(0xffffffffu, lB, off);
            }
            lrow[0] = lrow[0] * alA + lA;
            lrow[1] = lrow[1] * alB + lB;
            #pragma unroll
            for (int ni = 0; ni < 16; ni++) {
                o[ni][0] *= alA; o[ni][1] *= alA;
                o[ni][2] *= alB; o[ni][3] *= alB;
            }

            int prowA = hw * 64 + rowA;
            int prowB = hw * 64 + rowB;
            #pragma unroll
            for (int ni = 0; ni < 8; ni++) {
                int cn = ni * 8 + tg * 2;
                *(__half2*)&Ps[prowA * PS_STR + cn] = __floats2half2_rn(s[ni][0], s[ni][1]);
                *(__half2*)&Ps[prowB * PS_STR + cn] = __floats2half2_rn(s[ni][2], s[ni][3]);
            }
            __syncwarp();

            CP_WAIT1();
            __syncthreads();

            #pragma unroll
            for (int ks = 0; ks < 4; ++ks) {
                int kk = ks * 16;
                uint32_t pa4[4];
                uint32_t ap = sP + (uint32_t)(((hw * 64 + base + lr + lm * 8) * PS_STR + kk + lh * 8) * 2);
                LDSM_X4(pa4[0], pa4[1], pa4[2], pa4[3], ap);
                #pragma unroll
                for (int np = 0; np < 8; np++) {
                    uint32_t r0, r1, r2, r3;
                    uint32_t av = sV + (uint32_t)(((kk + p8 * 8 + lr) * US_STR
                                                   + np * 16 + p16 * 8) * 2);
                    LDSM_X4T(r0, r1, r2, r3, av);
                    mma_f16(o[2 * np],     pa4, r0, r1);
                    mma_f16(o[2 * np + 1], pa4, r2, r3);
                }
            }
            __syncthreads();

            if (more) {
                const __half* Vn = Vbase + (size_t)(kb + 1) * 64 * HD;
                #pragma unroll
                for (int it = 0; it < 4; ++it)
                    CP_ASYNC16(cpV[it], Vn + (size_t)cprow[it] * HD + cpc8[it]);
            }
            CP_COMMIT();
        }

        float ivA = 1.0f / lrow[0];
        float ivB = 1.0f / lrow[1];
        int qA = qb * 64 + base + g;
        int qB = qA + 8;
        size_t offA = (size_t)(b * TT + qA) * (NH * HD) + h * HD;
        size_t offB = (size_t)(b * TT + qB) * (NH * HD) + h * HD;
        #pragma unroll
        for (int ni = 0; ni < 16; ni++) {
            int dn = ni * 8 + tg * 2;
            *(__half2*)(ctx + offA + dn) = __floats2half2_rn(o[ni][0] * ivA, o[ni][1] * ivA);
            *(__half2*)(ctx + offB + dn) = __floats2half2_rn(o[ni][2] * ivB, o[ni][3] * ivB);
        }
    }
}

// ---------------------------- launch -----------------------------------------
extern "C" void kernel_launch(void* const* d_in, const int* in_sizes, int n_in,
                              void* d_out, int out_size)
{
    const float* x    = (const float*)d_in[0];
    // d_in[1] = attn_mask (pure causal; applied analytically)
    const float* Wq   = (const float*)d_in[2];
    const float* Wk   = (const float*)d_in[3];
    const float* Wv   = (const float*)d_in[4];
    const float* Wo   = (const float*)d_in[5];
    const float* qnw  = (const float*)d_in[6];
    const float* knw  = (const float*)d_in[7];
    float* out = (float*)d_out;

    float *qkvraw;
    __half *qt, *kt, *vt, *xh, *wqkv, *wo, *ctx;
    cudaGetSymbolAddress((void**)&qkvraw, g_qkvraw);
    cudaGetSymbolAddress((void**)&qt,   g_qt);
    cudaGetSymbolAddress((void**)&kt,   g_kt);
    cudaGetSymbolAddress((void**)&vt,   g_vt);
    cudaGetSymbolAddress((void**)&xh,   g_xh);
    cudaGetSymbolAddress((void**)&wqkv, g_wqkv);
    cudaGetSymbolAddress((void**)&wo,   g_wo);
    cudaGetSymbolAddress((void**)&ctx,  g_ctx);

    cudaFuncSetAttribute(flash_fp16_kernel, cudaFuncAttributeMaxDynamicSharedMemorySize,
                         FLASH_SMEM);

    // 0: rope table
    rope_table_kernel<<<TT / 2, 128>>>();
    // 1: merged prep (x->fp16, Wq/Wk/Wv/Wo transposed fp16)
    prep_kernel<<<PREP_BLOCKS, 256>>>(x, Wq, Wk, Wv, Wo, xh, wqkv, wo);
    // 2: fused QKV projection (N=4096)
    gemm_fp16_kernel<<<dim3(4096 / 128, MM / 128), 256>>>(xh, wqkv, qkvraw, MM, 4096, HH);
    // 3: merged RMSNorm/RoPE (Q,K) + V convert, warp-per-row
    normv_kernel<<<NORMV_ROWS / 8, 256>>>(qkvraw, qt, kt, vt, qnw, knw);
    // 4: flash attention (paired Q-tiles, uniform 33 iters/CTA)
    flash_fp16_kernel<<<dim3(NQB / 2, BB * NKV), 256, FLASH_SMEM>>>(qt, kt, vt, ctx);
    // 5: output projection
    gemm_fp16_kernel<<<dim3(2048 / 128, MM / 128), 256>>>(ctx, wo, out, MM, 2048, HH);
}

// round 14
// speedup vs baseline: 1.1785x; 1.0260x over previous
#include <cuda_runtime.h>
#include <cuda_fp16.h>
#include <cstdint>
#include <cstddef>
#include <math.h>

// Problem constants
#define BB   2
#define TT   2048
#define HH   2048
#define NH   16
#define NKV  8
#define HD   128
#define MM   (BB*TT)            // 4096 rows

// ---------------- scratch (static device globals; no allocation) -------------
__device__ float g_qkvraw[(size_t)MM * 4096];      // [b*T+t, {Q|K|V}]
__device__ __half g_qt[(size_t)BB * NH * TT * HD]; // [b,h,t,d] fp16
__device__ __half g_kt[(size_t)BB * NKV * TT * HD];
__device__ __half g_vt[(size_t)BB * NKV * TT * HD];
__device__ __half g_xh[(size_t)MM * HH];           // x fp16
__device__ __half g_wqkv[(size_t)4096 * 2048];     // [N=4096, K=2048] fp16 (Q|K|V rows)
__device__ __half g_wo[(size_t)2048 * 2048];       // Wo^T [N,K] fp16
__device__ __half g_ctx[(size_t)MM * HH];          // [b*T+t, h*HD+d] fp16
__device__ float g_cos[TT * 64];
__device__ float g_sin[TT * 64];

// ---------------- helpers ----------------------------------------------------
__device__ __forceinline__ uint32_t smem_u32(const void* p) {
    uint32_t a;
    asm("{ .reg .u64 t; cvta.to.shared.u64 t, %1; cvt.u32.u64 %0, t; }" : "=r"(a) : "l"(p));
    return a;
}

__device__ __forceinline__ void mma_f16(float c[4], const uint32_t a[4],
                                        uint32_t b0, uint32_t b1) {
    asm volatile(
        "mma.sync.aligned.m16n8k16.row.col.f32.f16.f16.f32 "
        "{%0,%1,%2,%3}, {%4,%5,%6,%7}, {%8,%9}, {%0,%1,%2,%3};\n"
        : "+f"(c[0]), "+f"(c[1]), "+f"(c[2]), "+f"(c[3])
        : "r"(a[0]), "r"(a[1]), "r"(a[2]), "r"(a[3]), "r"(b0), "r"(b1));
}

#define LDSM_X4(R0,R1,R2,R3,ADDR)                                              \
    asm volatile("ldmatrix.sync.aligned.m8n8.x4.shared.b16 {%0,%1,%2,%3}, [%4];" \
        : "=r"(R0), "=r"(R1), "=r"(R2), "=r"(R3) : "r"(ADDR))
#define LDSM_X4T(R0,R1,R2,R3,ADDR)                                             \
    asm volatile("ldmatrix.sync.aligned.m8n8.x4.trans.shared.b16 {%0,%1,%2,%3}, [%4];" \
        : "=r"(R0), "=r"(R1), "=r"(R2), "=r"(R3) : "r"(ADDR))

#define CP_ASYNC16(SMEM, GPTR) \
    asm volatile("cp.async.cg.shared.global [%0], [%1], 16;" :: "r"(SMEM), "l"(GPTR) : "memory")
#define CP_COMMIT() asm volatile("cp.async.commit_group;" ::: "memory")
#define CP_WAIT1()  asm volatile("cp.async.wait_group 1;" ::: "memory")

// ---------------- RoPE tables (fp64 angle, fp32 trig after reduction) ---------
__global__ void rope_table_kernel() {
    int t = blockIdx.x * 2 + (threadIdx.x >> 6);
    int j = threadIdx.x & 63;  // 0..63
    double inv = exp(-(double)j * (13.815510557964274 / 64.0)); // theta=1e6
    double ang = (double)t * inv;
    const double TWO_PI = 6.283185307179586476925286766559;
    double red = ang - TWO_PI * floor(ang * (1.0 / TWO_PI));
    float c, s;
    sincosf((float)red, &s, &c);
    g_cos[t * 64 + j] = c;
    g_sin[t * 64 + j] = s;
}

// ---------------- merged prep: x->fp16 + 4 weight transposes ------------------
#define PREP_BLOCKS 20480
__global__ __launch_bounds__(256) void prep_kernel(
    const float* __restrict__ x,
    const float* __restrict__ Wq, const float* __restrict__ Wk,
    const float* __restrict__ Wv, const float* __restrict__ Wo,
    __half* __restrict__ xh, __half* __restrict__ wqkv, __half* __restrict__ wo)
{
    __shared__ float t[32][33];
    int bid = blockIdx.x;
    int tid = threadIdx.x;

    if (bid < 8192) {
        size_t i = ((size_t)bid * 256 + tid) * 4;
        float4 v = *(const float4*)(x + i);
        *(__half2*)(xh + i)     = __floats2half2_rn(v.x, v.y);
        *(__half2*)(xh + i + 2) = __floats2half2_rn(v.z, v.w);
        return;
    }
    bid -= 8192;

    const float* W; __half* Wt; int N_;
    if (bid < 4096)      { W = Wq; Wt = wqkv;                        N_ = 2048; }
    else if (bid < 6144) { bid -= 4096; W = Wk; Wt = wqkv + (size_t)2048 * 2048; N_ = 1024; }
    else if (bid < 8192) { bid -= 6144; W = Wv; Wt = wqkv + (size_t)3072 * 2048; N_ = 1024; }
    else                 { bid -= 8192; W = Wo; Wt = wo;             N_ = 2048; }

    const int K = 2048;
    int tilesX = N_ / 32;
    int n0 = (bid % tilesX) * 32, k0 = (bid / tilesX) * 32;
    int tx = tid & 31, ty = tid >> 5;   // 32 x 8
    #pragma unroll
    for (int i = 0; i < 32; i += 8)
        t[ty + i][tx] = W[(size_t)(k0 + ty + i) * N_ + n0 + tx];
    __syncthreads();
    #pragma unroll
    for (int i = 0; i < 32; i += 8)
        Wt[(size_t)(n0 + ty + i) * K + k0 + tx] = __float2half(t[tx][ty + i]);
}

// ---------------- fp16 tensor-core GEMM: C[M,N] = A[M,K] @ B[N,K]^T -----------
// BK=32, double-buffered smem, ldmatrix fragment loads.
#define GAS 40   // smem row stride in halves (80B = 5x16B, odd -> ldmatrix clean)
#define GSTG (128 * GAS)
__global__ __launch_bounds__(256, 2) void gemm_fp16_kernel(
    const __half* __restrict__ A, const __half* __restrict__ Bm,
    float* __restrict__ C, int M, int N_, int K)
{
    __shared__ __half As[2 * GSTG];
    __shared__ __half Bs[2 * GSTG];

    int tid = threadIdx.x;
    int wid = tid >> 5, lane = tid & 31;
    int g = lane >> 2, tg = lane & 3;
    int lr = lane & 7;
    int lm = (lane >> 3) & 1;
    int lh = lane >> 4;
    int sel = lane >> 3;
    int warpRow = wid >> 1, warpCol = wid & 1;  // 4 x 2 warps
    int brow = blockIdx.y * 128, bcol = blockIdx.x * 128;

    int rowL[2], segL[2];
    #pragma unroll
    for (int it = 0; it < 2; ++it) {
        int idx = it * 256 + tid;
        rowL[it] = idx >> 2;
        segL[it] = (idx & 3) * 8;
    }
    const __half* ApL[2];
    const __half* BpL[2];
    #pragma unroll
    for (int it = 0; it < 2; ++it) {
        ApL[it] = A  + (size_t)(brow + rowL[it]) * K + segL[it];
        BpL[it] = Bm + (size_t)(bcol + rowL[it]) * K + segL[it];
    }

    uint32_t sA = smem_u32(As), sB = smem_u32(Bs);

    float acc[2][8][4];
    #pragma unroll
    for (int mi = 0; mi < 2; mi++)
        #pragma unroll
        for (int ni = 0; ni < 8; ni++)
            #pragma unroll
            for (int c = 0; c < 4; c++) acc[mi][ni][c] = 0.f;

    #pragma unroll
    for (int it = 0; it < 2; ++it) {
        *(int4*)&As[rowL[it] * GAS + segL[it]] = *(const int4*)ApL[it];
        *(int4*)&Bs[rowL[it] * GAS + segL[it]] = *(const int4*)BpL[it];
    }
    __syncthreads();

    int buf = 0;
    for (int k0 = 0; k0 < K; k0 += 32) {
        int4 pa[2], pb[2];
        bool more = (k0 + 32 < K);
        if (more) {
            #pragma unroll
            for (int it = 0; it < 2; ++it) {
                pa[it] = *(const int4*)(ApL[it] + k0 + 32);
                pb[it] = *(const int4*)(BpL[it] + k0 + 32);
            }
        }

        uint32_t bA = sA + buf * (GSTG * 2);
        uint32_t bB = sB + buf * (GSTG * 2);
        #pragma unroll
        for (int ks = 0; ks < 2; ++ks) {
            int kk = ks * 16;
            uint32_t af[2][4];
            #pragma unroll
            for (int mi = 0; mi < 2; mi++) {
                uint32_t addr = bA + (uint32_t)(((warpRow * 32 + mi * 16 + lr + lm * 8) * GAS
                                                 + kk + lh * 8) * 2);
                LDSM_X4(af[mi][0], af[mi][1], af[mi][2], af[mi][3], addr);
            }
            uint32_t bf[8][2];
            #pragma unroll
            for (int nb = 0; nb < 4; nb++) {
                int n0 = warpCol * 64 + nb * 16;
                uint32_t addr = bB + (uint32_t)(((n0 + lr + (sel >> 1) * 8) * GAS
                                                 + kk + (sel & 1) * 8) * 2);
                LDSM_X4(bf[2 * nb][0], bf[2 * nb][1], bf[2 * nb + 1][0], bf[2 * nb + 1][1], addr);
            }
            #pragma unroll
            for (int mi = 0; mi < 2; mi++)
                #pragma unroll
                for (int ni = 0; ni < 8; ni++)
                    mma_f16(acc[mi][ni], af[mi], bf[ni][0], bf[ni][1]);
        }

        if (more) {
            __half* Ad = As + (buf ^ 1) * GSTG;
            __half* Bd = Bs + (buf ^ 1) * GSTG;
            #pragma unroll
            for (int it = 0; it < 2; ++it) {
                *(int4*)&Ad[rowL[it] * GAS + segL[it]] = pa[it];
                *(int4*)&Bd[rowL[it] * GAS + segL[it]] = pb[it];
            }
        }
        __syncthreads();
        buf ^= 1;
    }

    #pragma unroll
    for (int mi = 0; mi < 2; mi++) {
        int r0 = brow + warpRow * 32 + mi * 16 + g;
        #pragma unroll
        for (int ni = 0; ni < 8; ni++) {
            int cn = bcol + warpCol * 64 + ni * 8 + tg * 2;
            *(float2*)(C + (size_t)r0 * N_ + cn) = make_float2(acc[mi][ni][0], acc[mi][ni][1]);
            *(float2*)(C + (size_t)(r0 + 8) * N_ + cn) = make_float2(acc[mi][ni][2], acc[mi][ni][3]);
        }
    }
}

// ------------- merged RMSNorm+RoPE (Q,K) + V convert, warp-per-row ------------
#define NORMV_ROWS (BB * TT * (NH + 2 * NKV))    // 131072
__global__ __launch_bounds__(256) void normv_kernel(
    const float* __restrict__ qkvraw,
    __half* __restrict__ qt, __half* __restrict__ kt, __half* __restrict__ vt,
    const float* __restrict__ qnw, const float* __restrict__ knw)
{
    int r = blockIdx.x * 8 + (threadIdx.x >> 5);
    int lane = threadIdx.x & 31;

    const float* src; __half* dst; const float* w; int nheads; bool donorm;
    if (r < BB * TT * NH) {
        src = qkvraw;            dst = qt; w = qnw; nheads = NH;  donorm = true;
    } else if (r < BB * TT * (NH + NKV)) {
        r -= BB * TT * NH;
        src = qkvraw + 2048;     dst = kt; w = knw; nheads = NKV; donorm = true;
    } else {
        r -= BB * TT * (NH + NKV);
        src = qkvraw + 3072;     dst = vt; w = qnw; nheads = NKV; donorm = false;
    }

    int h  = r % nheads;
    int bt = r / nheads;
    int t  = bt % TT;
    int b  = bt / TT;

    int d0 = lane * 4;
    float4 v = *(const float4*)(src + (size_t)bt * 4096 + h * HD + d0);
    __half* outp = dst + ((size_t)(b * nheads + h) * TT + t) * HD + d0;

    if (!donorm) {
        union { __half2 h2[2]; uint2 u; } pk;
        pk.h2[0] = __floats2half2_rn(v.x, v.y);
        pk.h2[1] = __floats2half2_rn(v.z, v.w);
        *(uint2*)outp = pk.u;
        return;
    }

    float ssq = v.x * v.x + v.y * v.y + v.z * v.z + v.w * v.w;
    #pragma unroll
    for (int off = 16; off; off >>= 1)
        ssq += __shfl_xor_sync(0xffffffffu, ssq, off);
    float rinv = rsqrtf(ssq * (1.0f / HD) + 1e-6f);

    float4 wv = *(const float4*)(w + d0);
    float n0 = v.x * rinv * wv.x;
    float n1 = v.y * rinv * wv.y;
    float n2 = v.z * rinv * wv.z;
    float n3 = v.w * rinv * wv.w;

    float p0 = __shfl_xor_sync(0xffffffffu, n0, 16);
    float p1 = __shfl_xor_sync(0xffffffffu, n1, 16);
    float p2 = __shfl_xor_sync(0xffffffffu, n2, 16);
    float p3 = __shfl_xor_sync(0xffffffffu, n3, 16);

    float sgn = (lane >= 16) ? 1.f : -1.f;
    int j0 = (lane & 15) * 4;
    float4 cc = *(const float4*)(g_cos + t * 64 + j0);
    float4 sc = *(const float4*)(g_sin + t * 64 + j0);

    float o0 = n0 * cc.x + sgn * p0 * sc.x;
    float o1 = n1 * cc.y + sgn * p1 * sc.y;
    float o2 = n2 * cc.z + sgn * p2 * sc.z;
    float o3 = n3 * cc.w + sgn * p3 * sc.w;

    union { __half2 h2[2]; uint2 u; } pk;
    pk.h2[0] = __floats2half2_rn(o0, o1);
    pk.h2[1] = __floats2half2_rn(o2, o3);
    *(uint2*)outp = pk.u;
}

// ------------- Causal flash attention: fp16 mma, cp.async pipeline ------------
// 512 triangular CTAs, launched longest-first: bid -> qb = 31 - bid/16 (LPT).
// 2 GQA heads per CTA.
#define US_STR 136   // halves; 272B rows -> ldmatrix conflict-free
#define PS_STR 72
#define FL_KV  (64 * US_STR)
#define FL_U   (128 * US_STR)
#define FLASH_SMEM ((2 * FL_KV + FL_U) * 2)
#define NQB    (TT / 64)         // 32 q-blocks

__global__ __launch_bounds__(256) void flash_fp16_kernel(
    const __half* __restrict__ Q, const __half* __restrict__ Kt,
    const __half* __restrict__ Vt, __half* __restrict__ ctx)
{
    extern __shared__ __half smh[];
    __half* Ks = smh;
    __half* Vs = smh + FL_KV;
    __half* Us = smh + 2 * FL_KV;
    __half* Ps = Us;

    int tid = threadIdx.x;
    int wid = tid >> 5, lane = tid & 31;
    int g = lane >> 2, tg = lane & 3;
    int lr = lane & 7;
    int lm = (lane >> 3) & 1;
    int lh = lane >> 4;
    int p8 = (lane >> 3) & 1;
    int p16 = lane >> 4;

    int hw = wid >> 2;
    int w4 = wid & 3;
    int base = w4 * 16;

    // LPT mapping: largest q-blocks first
    int bid = blockIdx.x;
    int qb = NQB - 1 - (bid >> 4);    // 31 down to 0
    int bk = bid & 15;                // 0..(BB*NKV-1)
    int b = bk / NKV, kvh = bk % NKV;
    int h = kvh * 2 + hw;

    const __half* Kbase = Kt + ((size_t)(b * NKV + kvh) * TT) * HD;
    const __half* Vbase = Vt + ((size_t)(b * NKV + kvh) * TT) * HD;

    uint32_t sK = smem_u32(Ks), sV = smem_u32(Vs), sU = smem_u32(Us), sP = sU;

    int cprow[4], cpc8[4];
    uint32_t cpK[4], cpV[4];
    #pragma unroll
    for (int it = 0; it < 4; ++it) {
        int idx = it * 256 + tid;
        cprow[it] = idx >> 4;
        cpc8[it]  = (idx & 15) * 8;
        cpK[it] = sK + (uint32_t)((cprow[it] * US_STR + cpc8[it]) * 2);
        cpV[it] = sV + (uint32_t)((cprow[it] * US_STR + cpc8[it]) * 2);
    }

    // prefetch K0, V0 (overlaps Q staging)
    #pragma unroll
    for (int it = 0; it < 4; ++it)
        CP_ASYNC16(cpK[it], Kbase + (size_t)cprow[it] * HD + cpc8[it]);
    CP_COMMIT();
    #pragma unroll
    for (int it = 0; it < 4; ++it)
        CP_ASYNC16(cpV[it], Vbase + (size_t)cprow[it] * HD + cpc8[it]);
    CP_COMMIT();

    // stage Q
    {
        const __half* Qh = Q + ((size_t)(b * NH + kvh * 2 + hw) * TT + qb * 64) * HD;
        int t128 = tid & 127;
        #pragma unroll
        for (int it = 0; it < 8; ++it) {
            int idx = it * 128 + t128;
            int r = idx >> 4;
            int c8 = (idx & 15) * 8;
            *(int4*)&Us[(hw * 64 + r) * US_STR + c8] =
                *(const int4*)(Qh + (size_t)r * HD + c8);
        }
    }
    __syncthreads();

    uint32_t qa[8][4];
    #pragma unroll
    for (int ks = 0; ks < 8; ++ks) {
        uint32_t au = sU + (uint32_t)(((hw * 64 + base + lr + lm * 8) * US_STR + ks * 16 + lh * 8) * 2);
        LDSM_X4(qa[ks][0], qa[ks][1], qa[ks][2], qa[ks][3], au);
    }

    float o[16][4];
    #pragma unroll
    for (int ni = 0; ni < 16; ni++)
        #pragma unroll
        for (int c = 0; c < 4; c++) o[ni][c] = 0.f;
    float mrow[2] = {-1e30f, -1e30f};
    float lrow[2] = {0.f, 0.f};

    const float scale = 0.08838834764831845f;   // 128^-0.5
    const float L2E = 1.44269504088896f;

    for (int kb = 0; kb <= qb; ++kb) {
        bool more = (kb < qb);
        CP_WAIT1();
        __syncthreads();

        float s[8][4];
        #pragma unroll
        for (int ni = 0; ni < 8; ni++)
            #pragma unroll
            for (int c = 0; c < 4; c++) s[ni][c] = 0.f;

        #pragma unroll
        for (int ks = 0; ks < 8; ++ks) {
            int kk = ks * 16;
            #pragma unroll
            for (int np = 0; np < 4; np++) {
                uint32_t r0, r1, r2, r3;
                uint32_t ak = sK + (uint32_t)(((np * 16 + p16 * 8 + lr) * US_STR
                                               + kk + p8 * 8) * 2);
                LDSM_X4(r0, r1, r2, r3, ak);
                mma_f16(s[2 * np],     qa[ks], r0, r1);
                mma_f16(s[2 * np + 1], qa[ks], r2, r3);
            }
        }
        __syncthreads();

        if (more) {
            const __half* Kn = Kbase + (size_t)(kb + 1) * 64 * HD;
            #pragma unroll
            for (int it = 0; it < 4; ++it)
                CP_ASYNC16(cpK[it], Kn + (size_t)cprow[it] * HD + cpc8[it]);
        }
        CP_COMMIT();

        bool diag = (kb == qb);
        int rowA = base + g;
        int rowB = rowA + 8;
        float mA = -1e30f, mB = -1e30f;
        #pragma unroll
        for (int ni = 0; ni < 8; ni++) {
            #pragma unroll
            for (int c = 0; c < 4; c++) {
                float sv = s[ni][c] * scale;
                if (diag) {
                    int kcol = ni * 8 + tg * 2 + (c & 1);
                    int qrow = (c < 2) ? rowA : rowB;
                    if (kcol > qrow) sv = -1e30f;
                }
                s[ni][c] = sv;
            }
            mA = fmaxf(mA, fmaxf(s[ni][0], s[ni][1]));
            mB = fmaxf(mB, fmaxf(s[ni][2], s[ni][3]));
        }
        #pragma unroll
        for (int off = 1; off < 4; off <<= 1) {
            mA = fmaxf(mA, __shfl_xor_sync(0xffffffffu, mA, off));
            mB = fmaxf(mB, __shfl_xor_sync(0xffffffffu, mB, off));
        }
        float mnA = fmaxf(mrow[0], mA);
        float mnB = fmaxf(mrow[1], mB);
        float alA = exp2f((mrow[0] - mnA) * L2E);
        float alB = exp2f((mrow[1] - mnB) * L2E);
        mrow[0] = mnA; mrow[1] = mnB;

        float lA = 0.f, lB = 0.f;
        #pragma unroll
        for (int ni = 0; ni < 8; ni++) {
            s[ni][0] = exp2f((s[ni][0] - mnA) * L2E);
            s[ni][1] = exp2f((s[ni][1] - mnA) * L2E);
            s[ni][2] = exp2f((s[ni][2] - mnB) * L2E);
            s[ni][3] = exp2f((s[ni][3] - mnB) * L2E);
            lA += s[ni][0] + s[ni][1];
            lB += s[ni][2] + s[ni][3];
        }
        #pragma unroll
        for (int off = 1; off < 4; off <<= 1) {
            lA += __shfl_xor_sync(0xffffffffu, lA, off);
            lB += __shfl_xor_sync(0xffffffffu, lB, off);
        }
        lrow[0] = lrow[0] * alA + lA;
        lrow[1] = lrow[1] * alB + lB;
        #pragma unroll
        for (int ni = 0; ni < 16; ni++) {
            o[ni][0] *= alA; o[ni][1] *= alA;
            o[ni][2] *= alB; o[ni][3] *= alB;
        }

        int prowA = hw * 64 + rowA;
        int prowB = hw * 64 + rowB;
        #pragma unroll
        for (int ni = 0; ni < 8; ni++) {
            int cn = ni * 8 + tg * 2;
            *(__half2*)&Ps[prowA * PS_STR + cn] = __floats2half2_rn(s[ni][0], s[ni][1]);
            *(__half2*)&Ps[prowB * PS_STR + cn] = __floats2half2_rn(s[ni][2], s[ni][3]);
        }
        __syncwarp();

        CP_WAIT1();
        __syncthreads();

        #pragma unroll
        for (int ks = 0; ks < 4; ++ks) {
            int kk = ks * 16;
            uint32_t pa4[4];
            uint32_t ap = sP + (uint32_t)(((hw * 64 + base + lr + lm * 8) * PS_STR + kk + lh * 8) * 2);
            LDSM_X4(pa4[0], pa4[1], pa4[2], pa4[3], ap);
            #pragma unroll
            for (int np = 0; np < 8; np++) {
                uint32_t r0, r1, r2, r3;
                uint32_t av = sV + (uint32_t)(((kk + p8 * 8 + lr) * US_STR
                                               + np * 16 + p16 * 8) * 2);
                LDSM_X4T(r0, r1, r2, r3, av);
                mma_f16(o[2 * np],     pa4, r0, r1);
                mma_f16(o[2 * np + 1], pa4, r2, r3);
            }
        }
        __syncthreads();

        if (more) {
            const __half* Vn = Vbase + (size_t)(kb + 1) * 64 * HD;
            #pragma unroll
            for (int it = 0; it < 4; ++it)
                CP_ASYNC16(cpV[it], Vn + (size_t)cprow[it] * HD + cpc8[it]);
        }
        CP_COMMIT();
    }

    float ivA = 1.0f / lrow[0];
    float ivB = 1.0f / lrow[1];
    int qA = qb * 64 + base + g;
    int qB = qA + 8;
    size_t offA = (size_t)(b * TT + qA) * (NH * HD) + h * HD;
    size_t offB = (size_t)(b * TT + qB) * (NH * HD) + h * HD;
    #pragma unroll
    for (int ni = 0; ni < 16; ni++) {
        int dn = ni * 8 + tg * 2;
        *(__half2*)(ctx + offA + dn) = __floats2half2_rn(o[ni][0] * ivA, o[ni][1] * ivA);
        *(__half2*)(ctx + offB + dn) = __floats2half2_rn(o[ni][2] * ivB, o[ni][3] * ivB);
    }
}

// ---------------------------- launch -----------------------------------------
extern "C" void kernel_launch(void* const* d_in, const int* in_sizes, int n_in,
                              void* d_out, int out_size)
{
    const float* x    = (const float*)d_in[0];
    // d_in[1] = attn_mask (pure causal; applied analytically)
    const float* Wq   = (const float*)d_in[2];
    const float* Wk   = (const float*)d_in[3];
    const float* Wv   = (const float*)d_in[4];
    const float* Wo   = (const float*)d_in[5];
    const float* qnw  = (const float*)d_in[6];
    const float* knw  = (const float*)d_in[7];
    float* out = (float*)d_out;

    float *qkvraw;
    __half *qt, *kt, *vt, *xh, *wqkv, *wo, *ctx;
    cudaGetSymbolAddress((void**)&qkvraw, g_qkvraw);
    cudaGetSymbolAddress((void**)&qt,   g_qt);
    cudaGetSymbolAddress((void**)&kt,   g_kt);
    cudaGetSymbolAddress((void**)&vt,   g_vt);
    cudaGetSymbolAddress((void**)&xh,   g_xh);
    cudaGetSymbolAddress((void**)&wqkv, g_wqkv);
    cudaGetSymbolAddress((void**)&wo,   g_wo);
    cudaGetSymbolAddress((void**)&ctx,  g_ctx);

    cudaFuncSetAttribute(flash_fp16_kernel, cudaFuncAttributeMaxDynamicSharedMemorySize,
                         FLASH_SMEM);

    // 0: rope table
    rope_table_kernel<<<TT / 2, 128>>>();
    // 1: merged prep (x->fp16, Wq/Wk/Wv/Wo transposed fp16)
    prep_kernel<<<PREP_BLOCKS, 256>>>(x, Wq, Wk, Wv, Wo, xh, wqkv, wo);
    // 2: fused QKV projection (N=4096)
    gemm_fp16_kernel<<<dim3(4096 / 128, MM / 128), 256>>>(xh, wqkv, qkvraw, MM, 4096, HH);
    // 3: merged RMSNorm/RoPE (Q,K) + V convert, warp-per-row
    normv_kernel<<<NORMV_ROWS / 8, 256>>>(qkvraw, qt, kt, vt, qnw, knw);
    // 4: flash attention (512 triangular CTAs, longest-first / LPT)
    flash_fp16_kernel<<<NQB * BB * NKV, 256, FLASH_SMEM>>>(qt, kt, vt, ctx);
    // 5: output projection
    gemm_fp16_kernel<<<dim3(2048 / 128, MM / 128), 256>>>(ctx, wo, out, MM, 2048, HH);
}

// round 15
// speedup vs baseline: 1.3335x; 1.1315x over previous
#include <cuda_runtime.h>
#include <cuda_fp16.h>
#include <cstdint>
#include <cstddef>
#include <math.h>

// Problem constants
#define BB   2
#define TT   2048
#define HH   2048
#define NH   16
#define NKV  8
#define HD   128
#define MM   (BB*TT)            // 4096 rows

// ---------------- scratch (static device globals; no allocation) -------------
__device__ float g_qkvraw[(size_t)MM * 4096];      // [b*T+t, {Q|K|V}]
__device__ __half g_qt[(size_t)BB * NH * TT * HD]; // [b,h,t,d] fp16
__device__ __half g_kt[(size_t)BB * NKV * TT * HD];
__device__ __half g_vt[(size_t)BB * NKV * TT * HD];
__device__ __half g_xh[(size_t)MM * HH];           // x fp16
__device__ __half g_wqkv[(size_t)4096 * 2048];     // [N=4096, K=2048] fp16 (Q|K|V rows)
__device__ __half g_wo[(size_t)2048 * 2048];       // Wo^T [N,K] fp16
__device__ __half g_ctx[(size_t)MM * HH];          // [b*T+t, h*HD+d] fp16
__device__ float g_cos[TT * 64];
__device__ float g_sin[TT * 64];

// ---------------- helpers ----------------------------------------------------
__device__ __forceinline__ uint32_t smem_u32(const void* p) {
    uint32_t a;
    asm("{ .reg .u64 t; cvta.to.shared.u64 t, %1; cvt.u32.u64 %0, t; }" : "=r"(a) : "l"(p));
    return a;
}

__device__ __forceinline__ void mma_f16(float c[4], const uint32_t a[4],
                                        uint32_t b0, uint32_t b1) {
    asm volatile(
        "mma.sync.aligned.m16n8k16.row.col.f32.f16.f16.f32 "
        "{%0,%1,%2,%3}, {%4,%5,%6,%7}, {%8,%9}, {%0,%1,%2,%3};\n"
        : "+f"(c[0]), "+f"(c[1]), "+f"(c[2]), "+f"(c[3])
        : "r"(a[0]), "r"(a[1]), "r"(a[2]), "r"(a[3]), "r"(b0), "r"(b1));
}

#define LDSM_X4(R0,R1,R2,R3,ADDR)                                              \
    asm volatile("ldmatrix.sync.aligned.m8n8.x4.shared.b16 {%0,%1,%2,%3}, [%4];" \
        : "=r"(R0), "=r"(R1), "=r"(R2), "=r"(R3) : "r"(ADDR))
#define LDSM_X4T(R0,R1,R2,R3,ADDR)                                             \
    asm volatile("ldmatrix.sync.aligned.m8n8.x4.trans.shared.b16 {%0,%1,%2,%3}, [%4];" \
        : "=r"(R0), "=r"(R1), "=r"(R2), "=r"(R3) : "r"(ADDR))

#define CP_ASYNC16(SMEM, GPTR) \
    asm volatile("cp.async.cg.shared.global [%0], [%1], 16;" :: "r"(SMEM), "l"(GPTR) : "memory")
#define CP_COMMIT() asm volatile("cp.async.commit_group;" ::: "memory")
#define CP_WAIT1()  asm volatile("cp.async.wait_group 1;" ::: "memory")

// ---------------- RoPE tables (fp64 angle, fp32 trig after reduction) ---------
__global__ void rope_table_kernel() {
    int t = blockIdx.x * 2 + (threadIdx.x >> 6);
    int j = threadIdx.x & 63;  // 0..63
    double inv = exp(-(double)j * (13.815510557964274 / 64.0)); // theta=1e6
    double ang = (double)t * inv;
    const double TWO_PI = 6.283185307179586476925286766559;
    double red = ang - TWO_PI * floor(ang * (1.0 / TWO_PI));
    float c, s;
    sincosf((float)red, &s, &c);
    g_cos[t * 64 + j] = c;
    g_sin[t * 64 + j] = s;
}

// ---------------- merged prep: x->fp16 + 4 weight transposes ------------------
#define PREP_BLOCKS 20480
__global__ __launch_bounds__(256) void prep_kernel(
    const float* __restrict__ x,
    const float* __restrict__ Wq, const float* __restrict__ Wk,
    const float* __restrict__ Wv, const float* __restrict__ Wo,
    __half* __restrict__ xh, __half* __restrict__ wqkv, __half* __restrict__ wo)
{
    __shared__ float t[32][33];
    int bid = blockIdx.x;
    int tid = threadIdx.x;

    if (bid < 8192) {
        size_t i = ((size_t)bid * 256 + tid) * 4;
        float4 v = *(const float4*)(x + i);
        *(__half2*)(xh + i)     = __floats2half2_rn(v.x, v.y);
        *(__half2*)(xh + i + 2) = __floats2half2_rn(v.z, v.w);
        return;
    }
    bid -= 8192;

    const float* W; __half* Wt; int N_;
    if (bid < 4096)      { W = Wq; Wt = wqkv;                        N_ = 2048; }
    else if (bid < 6144) { bid -= 4096; W = Wk; Wt = wqkv + (size_t)2048 * 2048; N_ = 1024; }
    else if (bid < 8192) { bid -= 6144; W = Wv; Wt = wqkv + (size_t)3072 * 2048; N_ = 1024; }
    else                 { bid -= 8192; W = Wo; Wt = wo;             N_ = 2048; }

    const int K = 2048;
    int tilesX = N_ / 32;
    int n0 = (bid % tilesX) * 32, k0 = (bid / tilesX) * 32;
    int tx = tid & 31, ty = tid >> 5;   // 32 x 8
    #pragma unroll
    for (int i = 0; i < 32; i += 8)
        t[ty + i][tx] = W[(size_t)(k0 + ty + i) * N_ + n0 + tx];
    __syncthreads();
    #pragma unroll
    for (int i = 0; i < 32; i += 8)
        Wt[(size_t)(n0 + ty + i) * K + k0 + tx] = __float2half(t[tx][ty + i]);
}

// ---------------- fp16 tensor-core GEMM: C[M,N] = A[M,K] @ B[N,K]^T -----------
// BK=32, 3-stage cp.async smem pipeline, ldmatrix fragment loads.
#define GAS 40   // smem row stride in halves (80B = 5x16B, odd -> ldmatrix clean)
#define GSTG (128 * GAS)                 // halves per tile per stage
#define GEMM_SMEM (3 * 2 * GSTG * 2)     // bytes: 3 stages x (A+B) x 2B = 61440
__global__ __launch_bounds__(256, 2) void gemm_fp16_kernel(
    const __half* __restrict__ A, const __half* __restrict__ Bm,
    float* __restrict__ C, int M, int N_, int K)
{
    extern __shared__ __half sm3[];
    __half* As = sm3;                    // 3 stages, GSTG halves each
    __half* Bs = sm3 + 3 * GSTG;

    int tid = threadIdx.x;
    int wid = tid >> 5, lane = tid & 31;
    int g = lane >> 2, tg = lane & 3;
    int lr = lane & 7;
    int lm = (lane >> 3) & 1;
    int lh = lane >> 4;
    int sel = lane >> 3;
    int warpRow = wid >> 1, warpCol = wid & 1;  // 4 x 2 warps
    int brow = blockIdx.y * 128, bcol = blockIdx.x * 128;

    int rowL[2], segL[2];
    #pragma unroll
    for (int it = 0; it < 2; ++it) {
        int idx = it * 256 + tid;
        rowL[it] = idx >> 2;
        segL[it] = (idx & 3) * 8;
    }
    const __half* ApL[2];
    const __half* BpL[2];
    #pragma unroll
    for (int it = 0; it < 2; ++it) {
        ApL[it] = A  + (size_t)(brow + rowL[it]) * K + segL[it];
        BpL[it] = Bm + (size_t)(bcol + rowL[it]) * K + segL[it];
    }

    uint32_t sA = smem_u32(As), sB = smem_u32(Bs);
    uint32_t cpA[2], cpB[2];
    #pragma unroll
    for (int it = 0; it < 2; ++it) {
        cpA[it] = sA + (uint32_t)((rowL[it] * GAS + segL[it]) * 2);
        cpB[it] = sB + (uint32_t)((rowL[it] * GAS + segL[it]) * 2);
    }
    const uint32_t STGB = GSTG * 2;      // stage stride in bytes

    float acc[2][8][4];
    #pragma unroll
    for (int mi = 0; mi < 2; mi++)
        #pragma unroll
        for (int ni = 0; ni < 8; ni++)
            #pragma unroll
            for (int c = 0; c < 4; c++) acc[mi][ni][c] = 0.f;

    // prologue: stages 0, 1 in flight
    #pragma unroll
    for (int st = 0; st < 2; ++st) {
        #pragma unroll
        for (int it = 0; it < 2; ++it) {
            CP_ASYNC16(cpA[it] + st * STGB, ApL[it] + st * 32);
            CP_ASYNC16(cpB[it] + st * STGB, BpL[it] + st * 32);
        }
        CP_COMMIT();
    }

    const int NK = K / 32;
    int st = 0;                           // stage of current iteration
    for (int itn = 0; itn < NK; ++itn) {
        CP_WAIT1();                       // stage itn complete
        __syncthreads();                  // prior iteration's readers done

        // issue stage itn+2 into buffer (st+2)%3 — flies under the mma below
        if (itn + 2 < NK) {
            int stw = st + 2; if (stw >= 3) stw -= 3;
            int k0 = (itn + 2) * 32;
            #pragma unroll
            for (int it = 0; it < 2; ++it) {
                CP_ASYNC16(cpA[it] + stw * STGB, ApL[it] + k0);
                CP_ASYNC16(cpB[it] + stw * STGB, BpL[it] + k0);
            }
        }
        CP_COMMIT();

        uint32_t bA = sA + st * STGB;
        uint32_t bB = sB + st * STGB;
        #pragma unroll
        for (int ks = 0; ks < 2; ++ks) {
            int kk = ks * 16;
            uint32_t af[2][4];
            #pragma unroll
            for (int mi = 0; mi < 2; mi++) {
                uint32_t addr = bA + (uint32_t)(((warpRow * 32 + mi * 16 + lr + lm * 8) * GAS
                                                 + kk + lh * 8) * 2);
                LDSM_X4(af[mi][0], af[mi][1], af[mi][2], af[mi][3], addr);
            }
            uint32_t bf[8][2];
            #pragma unroll
            for (int nb = 0; nb < 4; nb++) {
                int n0 = warpCol * 64 + nb * 16;
                uint32_t addr = bB + (uint32_t)(((n0 + lr + (sel >> 1) * 8) * GAS
                                                 + kk + (sel & 1) * 8) * 2);
                LDSM_X4(bf[2 * nb][0], bf[2 * nb][1], bf[2 * nb + 1][0], bf[2 * nb + 1][1], addr);
            }
            #pragma unroll
            for (int mi = 0; mi < 2; mi++)
                #pragma unroll
                for (int ni = 0; ni < 8; ni++)
                    mma_f16(acc[mi][ni], af[mi], bf[ni][0], bf[ni][1]);
        }

        if (++st >= 3) st = 0;
    }

    __syncthreads();
    #pragma unroll
    for (int mi = 0; mi < 2; mi++) {
        int r0 = brow + warpRow * 32 + mi * 16 + g;
        #pragma unroll
        for (int ni = 0; ni < 8; ni++) {
            int cn = bcol + warpCol * 64 + ni * 8 + tg * 2;
            *(float2*)(C + (size_t)r0 * N_ + cn) = make_float2(acc[mi][ni][0], acc[mi][ni][1]);
            *(float2*)(C + (size_t)(r0 + 8) * N_ + cn) = make_float2(acc[mi][ni][2], acc[mi][ni][3]);
        }
    }
}

// ------------- merged RMSNorm+RoPE (Q,K) + V convert, warp-per-row ------------
#define NORMV_ROWS (BB * TT * (NH + 2 * NKV))    // 131072
__global__ __launch_bounds__(256) void normv_kernel(
    const float* __restrict__ qkvraw,
    __half* __restrict__ qt, __half* __restrict__ kt, __half* __restrict__ vt,
    const float* __restrict__ qnw, const float* __restrict__ knw)
{
    int r = blockIdx.x * 8 + (threadIdx.x >> 5);
    int lane = threadIdx.x & 31;

    const float* src; __half* dst; const float* w; int nheads; bool donorm;
    if (r < BB * TT * NH) {
        src = qkvraw;            dst = qt; w = qnw; nheads = NH;  donorm = true;
    } else if (r < BB * TT * (NH + NKV)) {
        r -= BB * TT * NH;
        src = qkvraw + 2048;     dst = kt; w = knw; nheads = NKV; donorm = true;
    } else {
        r -= BB * TT * (NH + NKV);
        src = qkvraw + 3072;     dst = vt; w = qnw; nheads = NKV; donorm = false;
    }

    int h  = r % nheads;
    int bt = r / nheads;
    int t  = bt % TT;
    int b  = bt / TT;

    int d0 = lane * 4;
    float4 v = *(const float4*)(src + (size_t)bt * 4096 + h * HD + d0);
    __half* outp = dst + ((size_t)(b * nheads + h) * TT + t) * HD + d0;

    if (!donorm) {
        union { __half2 h2[2]; uint2 u; } pk;
        pk.h2[0] = __floats2half2_rn(v.x, v.y);
        pk.h2[1] = __floats2half2_rn(v.z, v.w);
        *(uint2*)outp = pk.u;
        return;
    }

    float ssq = v.x * v.x + v.y * v.y + v.z * v.z + v.w * v.w;
    #pragma unroll
    for (int off = 16; off; off >>= 1)
        ssq += __shfl_xor_sync(0xffffffffu, ssq, off);
    float rinv = rsqrtf(ssq * (1.0f / HD) + 1e-6f);

    float4 wv = *(const float4*)(w + d0);
    float n0 = v.x * rinv * wv.x;
    float n1 = v.y * rinv * wv.y;
    float n2 = v.z * rinv * wv.z;
    float n3 = v.w * rinv * wv.w;

    float p0 = __shfl_xor_sync(0xffffffffu, n0, 16);
    float p1 = __shfl_xor_sync(0xffffffffu, n1, 16);
    float p2 = __shfl_xor_sync(0xffffffffu, n2, 16);
    float p3 = __shfl_xor_sync(0xffffffffu, n3, 16);

    float sgn = (lane >= 16) ? 1.f : -1.f;
    int j0 = (lane & 15) * 4;
    float4 cc = *(const float4*)(g_cos + t * 64 + j0);
    float4 sc = *(const float4*)(g_sin + t * 64 + j0);

    float o0 = n0 * cc.x + sgn * p0 * sc.x;
    float o1 = n1 * cc.y + sgn * p1 * sc.y;
    float o2 = n2 * cc.z + sgn * p2 * sc.z;
    float o3 = n3 * cc.w + sgn * p3 * sc.w;

    union { __half2 h2[2]; uint2 u; } pk;
    pk.h2[0] = __floats2half2_rn(o0, o1);
    pk.h2[1] = __floats2half2_rn(o2, o3);
    *(uint2*)outp = pk.u;
}

// ------------- Causal flash attention: fp16 mma, cp.async pipeline ------------
// 512 triangular CTAs, launched longest-first: bid -> qb = 31 - bid/16 (LPT).
// 2 GQA heads per CTA.
#define US_STR 136   // halves; 272B rows -> ldmatrix conflict-free
#define PS_STR 72
#define FL_KV  (64 * US_STR)
#define FL_U   (128 * US_STR)
#define FLASH_SMEM ((2 * FL_KV + FL_U) * 2)
#define NQB    (TT / 64)         // 32 q-blocks

__global__ __launch_bounds__(256) void flash_fp16_kernel(
    const __half* __restrict__ Q, const __half* __restrict__ Kt,
    const __half* __restrict__ Vt, __half* __restrict__ ctx)
{
    extern __shared__ __half smh[];
    __half* Ks = smh;
    __half* Vs = smh + FL_KV;
    __half* Us = smh + 2 * FL_KV;
    __half* Ps = Us;

    int tid = threadIdx.x;
    int wid = tid >> 5, lane = tid & 31;
    int g = lane >> 2, tg = lane & 3;
    int lr = lane & 7;
    int lm = (lane >> 3) & 1;
    int lh = lane >> 4;
    int p8 = (lane >> 3) & 1;
    int p16 = lane >> 4;

    int hw = wid >> 2;
    int w4 = wid & 3;
    int base = w4 * 16;

    // LPT mapping: largest q-blocks first
    int bid = blockIdx.x;
    int qb = NQB - 1 - (bid >> 4);    // 31 down to 0
    int bk = bid & 15;                // 0..(BB*NKV-1)
    int b = bk / NKV, kvh = bk % NKV;
    int h = kvh * 2 + hw;

    const __half* Kbase = Kt + ((size_t)(b * NKV + kvh) * TT) * HD;
    const __half* Vbase = Vt + ((size_t)(b * NKV + kvh) * TT) * HD;

    uint32_t sK = smem_u32(Ks), sV = smem_u32(Vs), sU = smem_u32(Us), sP = sU;

    int cprow[4], cpc8[4];
    uint32_t cpK[4], cpV[4];
    #pragma unroll
    for (int it = 0; it < 4; ++it) {
        int idx = it * 256 + tid;
        cprow[it] = idx >> 4;
        cpc8[it]  = (idx & 15) * 8;
        cpK[it] = sK + (uint32_t)((cprow[it] * US_STR + cpc8[it]) * 2);
        cpV[it] = sV + (uint32_t)((cprow[it] * US_STR + cpc8[it]) * 2);
    }

    // prefetch K0, V0 (overlaps Q staging)
    #pragma unroll
    for (int it = 0; it < 4; ++it)
        CP_ASYNC16(cpK[it], Kbase + (size_t)cprow[it] * HD + cpc8[it]);
    CP_COMMIT();
    #pragma unroll
    for (int it = 0; it < 4; ++it)
        CP_ASYNC16(cpV[it], Vbase + (size_t)cprow[it] * HD + cpc8[it]);
    CP_COMMIT();

    // stage Q
    {
        const __half* Qh = Q + ((size_t)(b * NH + kvh * 2 + hw) * TT + qb * 64) * HD;
        int t128 = tid & 127;
        #pragma unroll
        for (int it = 0; it < 8; ++it) {
            int idx = it * 128 + t128;
            int r = idx >> 4;
            int c8 = (idx & 15) * 8;
            *(int4*)&Us[(hw * 64 + r) * US_STR + c8] =
                *(const int4*)(Qh + (size_t)r * HD + c8);
        }
    }
    __syncthreads();

    uint32_t qa[8][4];
    #pragma unroll
    for (int ks = 0; ks < 8; ++ks) {
        uint32_t au = sU + (uint32_t)(((hw * 64 + base + lr + lm * 8) * US_STR + ks * 16 + lh * 8) * 2);
        LDSM_X4(qa[ks][0], qa[ks][1], qa[ks][2], qa[ks][3], au);
    }

    float o[16][4];
    #pragma unroll
    for (int ni = 0; ni < 16; ni++)
        #pragma unroll
        for (int c = 0; c < 4; c++) o[ni][c] = 0.f;
    float mrow[2] = {-1e30f, -1e30f};
    float lrow[2] = {0.f, 0.f};

    const float scale = 0.08838834764831845f;   // 128^-0.5
    const float L2E = 1.44269504088896f;

    for (int kb = 0; kb <= qb; ++kb) {
        bool more = (kb < qb);
        CP_WAIT1();
        __syncthreads();

        float s[8][4];
        #pragma unroll
        for (int ni = 0; ni < 8; ni++)
            #pragma unroll
            for (int c = 0; c < 4; c++) s[ni][c] = 0.f;

        #pragma unroll
        for (int ks = 0; ks < 8; ++ks) {
            int kk = ks * 16;
            #pragma unroll
            for (int np = 0; np < 4; np++) {
                uint32_t r0, r1, r2, r3;
                uint32_t ak = sK + (uint32_t)(((np * 16 + p16 * 8 + lr) * US_STR
                                               + kk + p8 * 8) * 2);
                LDSM_X4(r0, r1, r2, r3, ak);
                mma_f16(s[2 * np],     qa[ks], r0, r1);
                mma_f16(s[2 * np + 1], qa[ks], r2, r3);
            }
        }
        __syncthreads();

        if (more) {
            const __half* Kn = Kbase + (size_t)(kb + 1) * 64 * HD;
            #pragma unroll
            for (int it = 0; it < 4; ++it)
                CP_ASYNC16(cpK[it], Kn + (size_t)cprow[it] * HD + cpc8[it]);
        }
        CP_COMMIT();

        bool diag = (kb == qb);
        int rowA = base + g;
        int rowB = rowA + 8;
        float mA = -1e30f, mB = -1e30f;
        #pragma unroll
        for (int ni = 0; ni < 8; ni++) {
            #pragma unroll
            for (int c = 0; c < 4; c++) {
                float sv = s[ni][c] * scale;
                if (diag) {
                    int kcol = ni * 8 + tg * 2 + (c & 1);
                    int qrow = (c < 2) ? rowA : rowB;
                    if (kcol > qrow) sv = -1e30f;
                }
                s[ni][c] = sv;
            }
            mA = fmaxf(mA, fmaxf(s[ni][0], s[ni][1]));
            mB = fmaxf(mB, fmaxf(s[ni][2], s[ni][3]));
        }
        #pragma unroll
        for (int off = 1; off < 4; off <<= 1) {
            mA = fmaxf(mA, __shfl_xor_sync(0xffffffffu, mA, off));
            mB = fmaxf(mB, __shfl_xor_sync(0xffffffffu, mB, off));
        }
        float mnA = fmaxf(mrow[0], mA);
        float mnB = fmaxf(mrow[1], mB);
        float alA = exp2f((mrow[0] - mnA) * L2E);
        float alB = exp2f((mrow[1] - mnB) * L2E);
        mrow[0] = mnA; mrow[1] = mnB;

        float lA = 0.f, lB = 0.f;
        #pragma unroll
        for (int ni = 0; ni < 8; ni++) {
            s[ni][0] = exp2f((s[ni][0] - mnA) * L2E);
            s[ni][1] = exp2f((s[ni][1] - mnA) * L2E);
            s[ni][2] = exp2f((s[ni][2] - mnB) * L2E);
            s[ni][3] = exp2f((s[ni][3] - mnB) * L2E);
            lA += s[ni][0] + s[ni][1];
            lB += s[ni][2] + s[ni][3];
        }
        #pragma unroll
        for (int off = 1; off < 4; off <<= 1) {
            lA += __shfl_xor_sync(0xffffffffu, lA, off);
            lB += __shfl_xor_sync(0xffffffffu, lB, off);
        }
        lrow[0] = lrow[0] * alA + lA;
        lrow[1] = lrow[1] * alB + lB;
        #pragma unroll
        for (int ni = 0; ni < 16; ni++) {
            o[ni][0] *= alA; o[ni][1] *= alA;
            o[ni][2] *= alB; o[ni][3] *= alB;
        }

        int prowA = hw * 64 + rowA;
        int prowB = hw * 64 + rowB;
        #pragma unroll
        for (int ni = 0; ni < 8; ni++) {
            int cn = ni * 8 + tg * 2;
            *(__half2*)&Ps[prowA * PS_STR + cn] = __floats2half2_rn(s[ni][0], s[ni][1]);
            *(__half2*)&Ps[prowB * PS_STR + cn] = __floats2half2_rn(s[ni][2], s[ni][3]);
        }
        __syncwarp();

        CP_WAIT1();
        __syncthreads();

        #pragma unroll
        for (int ks = 0; ks < 4; ++ks) {
            int kk = ks * 16;
            uint32_t pa4[4];
            uint32_t ap = sP + (uint32_t)(((hw * 64 + base + lr + lm * 8) * PS_STR + kk + lh * 8) * 2);
            LDSM_X4(pa4[0], pa4[1], pa4[2], pa4[3], ap);
            #pragma unroll
            for (int np = 0; np < 8; np++) {
                uint32_t r0, r1, r2, r3;
                uint32_t av = sV + (uint32_t)(((kk + p8 * 8 + lr) * US_STR
                                               + np * 16 + p16 * 8) * 2);
                LDSM_X4T(r0, r1, r2, r3, av);
                mma_f16(o[2 * np],     pa4, r0, r1);
                mma_f16(o[2 * np + 1], pa4, r2, r3);
            }
        }
        __syncthreads();

        if (more) {
            const __half* Vn = Vbase + (size_t)(kb + 1) * 64 * HD;
            #pragma unroll
            for (int it = 0; it < 4; ++it)
                CP_ASYNC16(cpV[it], Vn + (size_t)cprow[it] * HD + cpc8[it]);
        }
        CP_COMMIT();
    }

    float ivA = 1.0f / lrow[0];
    float ivB = 1.0f / lrow[1];
    int qA = qb * 64 + base + g;
    int qB = qA + 8;
    size_t offA = (size_t)(b * TT + qA) * (NH * HD) + h * HD;
    size_t offB = (size_t)(b * TT + qB) * (NH * HD) + h * HD;
    #pragma unroll
    for (int ni = 0; ni < 16; ni++) {
        int dn = ni * 8 + tg * 2;
        *(__half2*)(ctx + offA + dn) = __floats2half2_rn(o[ni][0] * ivA, o[ni][1] * ivA);
        *(__half2*)(ctx + offB + dn) = __floats2half2_rn(o[ni][2] * ivB, o[ni][3] * ivB);
    }
}

// ---------------------------- launch -----------------------------------------
extern "C" void kernel_launch(void* const* d_in, const int* in_sizes, int n_in,
                              void* d_out, int out_size)
{
    const float* x    = (const float*)d_in[0];
    // d_in[1] = attn_mask (pure causal; applied analytically)
    const float* Wq   = (const float*)d_in[2];
    const float* Wk   = (const float*)d_in[3];
    const float* Wv   = (const float*)d_in[4];
    const float* Wo   = (const float*)d_in[5];
    const float* qnw  = (const float*)d_in[6];
    const float* knw  = (const float*)d_in[7];
    float* out = (float*)d_out;

    float *qkvraw;
    __half *qt, *kt, *vt, *xh, *wqkv, *wo, *ctx;
    cudaGetSymbolAddress((void**)&qkvraw, g_qkvraw);
    cudaGetSymbolAddress((void**)&qt,   g_qt);
    cudaGetSymbolAddress((void**)&kt,   g_kt);
    cudaGetSymbolAddress((void**)&vt,   g_vt);
    cudaGetSymbolAddress((void**)&xh,   g_xh);
    cudaGetSymbolAddress((void**)&wqkv, g_wqkv);
    cudaGetSymbolAddress((void**)&wo,   g_wo);
    cudaGetSymbolAddress((void**)&ctx,  g_ctx);

    cudaFuncSetAttribute(flash_fp16_kernel, cudaFuncAttributeMaxDynamicSharedMemorySize,
                         FLASH_SMEM);
    cudaFuncSetAttribute(gemm_fp16_kernel, cudaFuncAttributeMaxDynamicSharedMemorySize,
                         GEMM_SMEM);

    // 0: rope table
    rope_table_kernel<<<TT / 2, 128>>>();
    // 1: merged prep (x->fp16, Wq/Wk/Wv/Wo transposed fp16)
    prep_kernel<<<PREP_BLOCKS, 256>>>(x, Wq, Wk, Wv, Wo, xh, wqkv, wo);
    // 2: fused QKV projection (N=4096, 3-stage cp.async)
    gemm_fp16_kernel<<<dim3(4096 / 128, MM / 128), 256, GEMM_SMEM>>>(
        xh, wqkv, qkvraw, MM, 4096, HH);
    // 3: merged RMSNorm/RoPE (Q,K) + V convert, warp-per-row
    normv_kernel<<<NORMV_ROWS / 8, 256>>>(qkvraw, qt, kt, vt, qnw, knw);
    // 4: flash attention (512 triangular CTAs, longest-first / LPT)
    flash_fp16_kernel<<<NQB * BB * NKV, 256, FLASH_SMEM>>>(qt, kt, vt, ctx);
    // 5: output projection
    gemm_fp16_kernel<<<dim3(2048 / 128, MM / 128), 256, GEMM_SMEM>>>(
        ctx, wo, out, MM, 2048, HH);
}